// round 2
// baseline (speedup 1.0000x reference)
#include <cuda_runtime.h>
#include <cuda_bf16.h>
#include <mma.h>

using namespace nvcuda;

// ---------------------------------------------------------------------------
// Dims (fixed): B=2, T=2048, HID=2048, H=16, DK=DV=128, W=4; rows = B*T = 4096
// ---------------------------------------------------------------------------

// Scratch (device globals; allocation in kernel_launch is forbidden)
__device__ float g_q   [4096ll * 2048];   // q (then qn in-place)
__device__ float g_k   [4096ll * 2048];   // k (then kn in-place)
__device__ float g_v   [4096ll * 2048];   // v = x@Wv
__device__ float g_v2  [4096ll * 2048];   // silu(conv(v))
__device__ float g_hpre[4096ll * 2048];   // gen hidden (then og)
__device__ float g_kern[4096ll * 8192];   // conv kernels (then xg)
__device__ float g_o   [4096ll * 2048];   // recurrence output
__device__ float g_beta [4096 * 16];
__device__ float g_decay[4096 * 16];

__device__ __forceinline__ float sigmoidf_(float x) { return 1.f / (1.f + expf(-x)); }

// Split one fp32 into bf16 hi + bf16 lo (lo = round(x - hi)); ~16-bit mantissa total.
__device__ __forceinline__ void split_pair(float x, float y,
                                           __nv_bfloat162& hi, __nv_bfloat162& lo)
{
    __nv_bfloat16 hx = __float2bfloat16_rn(x);
    __nv_bfloat16 hy = __float2bfloat16_rn(y);
    __nv_bfloat16 lx = __float2bfloat16_rn(x - __bfloat162float(hx));
    __nv_bfloat16 ly = __float2bfloat16_rn(y - __bfloat162float(hy));
    hi = __nv_bfloat162(hx, hy);
    lo = __nv_bfloat162(lx, ly);
}

// ---------------------------------------------------------------------------
// Split-bf16 wmma GEMM: C[M,N] = A[M,K] @ B[K,N] with fp32-equivalent-ish
// precision: A = Ah+Al, B = Bh+Bl (bf16), acc += Ah*Bh + Ah*Bl + Al*Bh (fp32).
// MODE 0: plain store.  MODE 1: C += result, then SiLU.  MODE 2: result + bias.
// Tiles: CTA 128x128, K-tile 16, double-buffered smem, 8 warps (2x4), each
// warp 64x32 (4x2 fragments of 16x16).
// ---------------------------------------------------------------------------
template <int MODE>
__global__ void __launch_bounds__(256, 1) gemm_kernel(
    const float* __restrict__ A, const float* __restrict__ Bm,
    float* __restrict__ C, const float* __restrict__ bias,
    int M, int N, int K)
{
    __shared__ __align__(16) char smem_raw[41984];
    // per stage (20992 B): Ah(128x24 bf16)=6144, Al=6144, Bh(16x136)=4352, Bl=4352
    const int tid = threadIdx.x;
    const int wid = tid >> 5;
    const int wm  = wid >> 2;   // 0..1
    const int wn  = wid & 3;    // 0..3
    const int m0  = blockIdx.y << 7;
    const int n0  = blockIdx.x << 7;

    auto Ah = [&](int s) -> __nv_bfloat16* { return (__nv_bfloat16*)(smem_raw + s * 20992); };
    auto Al = [&](int s) -> __nv_bfloat16* { return (__nv_bfloat16*)(smem_raw + s * 20992 + 6144); };
    auto Bh = [&](int s) -> __nv_bfloat16* { return (__nv_bfloat16*)(smem_raw + s * 20992 + 12288); };
    auto Bl = [&](int s) -> __nv_bfloat16* { return (__nv_bfloat16*)(smem_raw + s * 20992 + 16640); };

    wmma::fragment<wmma::accumulator, 16, 16, 16, float> acc[4][2];
#pragma unroll
    for (int i = 0; i < 4; ++i)
#pragma unroll
        for (int j = 0; j < 2; ++j) wmma::fill_fragment(acc[i][j], 0.f);

    // ---- stage a K-tile from registers to smem (with hi/lo split) ----
    auto stage_store = [&](int s, const float4 (&ra)[2], const float4 (&rb)[2]) {
        __nv_bfloat16* ah = Ah(s); __nv_bfloat16* al = Al(s);
        __nv_bfloat16* bh = Bh(s); __nv_bfloat16* bl = Bl(s);
#pragma unroll
        for (int j = 0; j < 2; ++j) {
            int lin = tid + j * 256;
            int r = lin >> 2, c = (lin & 3) << 2;     // A: 128 x 16
            __nv_bfloat162 h0, l0, h1, l1;
            split_pair(ra[j].x, ra[j].y, h0, l0);
            split_pair(ra[j].z, ra[j].w, h1, l1);
            *(__nv_bfloat162*)(ah + r * 24 + c)     = h0;
            *(__nv_bfloat162*)(ah + r * 24 + c + 2) = h1;
            *(__nv_bfloat162*)(al + r * 24 + c)     = l0;
            *(__nv_bfloat162*)(al + r * 24 + c + 2) = l1;
        }
#pragma unroll
        for (int j = 0; j < 2; ++j) {
            int lin = tid + j * 256;
            int r = lin >> 5, c = (lin & 31) << 2;    // B: 16 x 128
            __nv_bfloat162 h0, l0, h1, l1;
            split_pair(rb[j].x, rb[j].y, h0, l0);
            split_pair(rb[j].z, rb[j].w, h1, l1);
            *(__nv_bfloat162*)(bh + r * 136 + c)     = h0;
            *(__nv_bfloat162*)(bh + r * 136 + c + 2) = h1;
            *(__nv_bfloat162*)(bl + r * 136 + c)     = l0;
            *(__nv_bfloat162*)(bl + r * 136 + c + 2) = l1;
        }
    };
    auto tile_load = [&](int kt, float4 (&ra)[2], float4 (&rb)[2]) {
        const float* Ag = A + (size_t)m0 * K + kt * 16;
#pragma unroll
        for (int j = 0; j < 2; ++j) {
            int lin = tid + j * 256;
            int r = lin >> 2, c = (lin & 3) << 2;
            ra[j] = *(const float4*)(Ag + (size_t)r * K + c);
        }
        const float* Bg = Bm + (size_t)kt * 16 * N + n0;
#pragma unroll
        for (int j = 0; j < 2; ++j) {
            int lin = tid + j * 256;
            int r = lin >> 5, c = (lin & 31) << 2;
            rb[j] = *(const float4*)(Bg + (size_t)r * N + c);
        }
    };

    // prologue
    {
        float4 ra[2], rb[2];
        tile_load(0, ra, rb);
        stage_store(0, ra, rb);
    }
    __syncthreads();

    const int KT = K >> 4;
    float4 ra[2], rb[2];
    for (int kt = 0; kt < KT; ++kt) {
        const int s = kt & 1;
        const bool more = (kt + 1) < KT;
        if (more) tile_load(kt + 1, ra, rb);

        wmma::fragment<wmma::matrix_a, 16, 16, 16, __nv_bfloat16, wmma::row_major> afh[4], afl[4];
        wmma::fragment<wmma::matrix_b, 16, 16, 16, __nv_bfloat16, wmma::row_major> bfh[2], bfl[2];
        {
            __nv_bfloat16* ah = Ah(s); __nv_bfloat16* al = Al(s);
            __nv_bfloat16* bh = Bh(s); __nv_bfloat16* bl = Bl(s);
#pragma unroll
            for (int mi = 0; mi < 4; ++mi) {
                wmma::load_matrix_sync(afh[mi], ah + (wm * 64 + mi * 16) * 24, 24);
                wmma::load_matrix_sync(afl[mi], al + (wm * 64 + mi * 16) * 24, 24);
            }
#pragma unroll
            for (int ni = 0; ni < 2; ++ni) {
                wmma::load_matrix_sync(bfh[ni], bh + wn * 32 + ni * 16, 136);
                wmma::load_matrix_sync(bfl[ni], bl + wn * 32 + ni * 16, 136);
            }
        }
#pragma unroll
        for (int mi = 0; mi < 4; ++mi)
#pragma unroll
            for (int ni = 0; ni < 2; ++ni) {
                wmma::mma_sync(acc[mi][ni], afh[mi], bfl[ni], acc[mi][ni]);
                wmma::mma_sync(acc[mi][ni], afl[mi], bfh[ni], acc[mi][ni]);
                wmma::mma_sync(acc[mi][ni], afh[mi], bfh[ni], acc[mi][ni]);
            }

        if (more) {
            stage_store(s ^ 1, ra, rb);
            __syncthreads();
        }
    }

    // epilogue through smem staging, 64-row halves
    float* epi = (float*)smem_raw;
#pragma unroll
    for (int half = 0; half < 2; ++half) {
        __syncthreads();
        if (wm == half) {
#pragma unroll
            for (int mi = 0; mi < 4; ++mi)
#pragma unroll
                for (int ni = 0; ni < 2; ++ni)
                    wmma::store_matrix_sync(epi + (mi * 16) * 132 + wn * 32 + ni * 16,
                                            acc[mi][ni], 132, wmma::mem_row_major);
        }
        __syncthreads();
#pragma unroll
        for (int j = 0; j < 8; ++j) {
            int lin = tid + j * 256;
            int r = lin >> 5, c = (lin & 31) << 2;
            float4 v = *(float4*)(epi + r * 132 + c);
            size_t go = (size_t)(m0 + half * 64 + r) * N + n0 + c;
            if (MODE == 1) {
                float4 p = *(const float4*)(C + go);
                v.x += p.x; v.y += p.y; v.z += p.z; v.w += p.w;
                v.x = v.x * sigmoidf_(v.x);
                v.y = v.y * sigmoidf_(v.y);
                v.z = v.z * sigmoidf_(v.z);
                v.w = v.w * sigmoidf_(v.w);
            } else if (MODE == 2) {
                const float* bp = bias + n0 + c;
                v.x += bp[0]; v.y += bp[1]; v.z += bp[2]; v.w += bp[3];
            }
            *(float4*)(C + go) = v;
        }
    }
}

// ---------------------------------------------------------------------------
// Dynamic short conv (W=4, causal) + SiLU.  kern: [rows, 2048, 4], v: [rows, 2048]
// ---------------------------------------------------------------------------
__global__ void __launch_bounds__(256) conv_kernel(
    const float* __restrict__ kern, const float* __restrict__ v, float* __restrict__ v2)
{
    int idx = blockIdx.x * 256 + threadIdx.x;   // rows*2048 threads
    int row = idx >> 11;
    int d   = idx & 2047;
    int t   = row & 2047;                       // T = 2048
    float4 kf = *(const float4*)(kern + (size_t)row * 8192 + d * 4);
    size_t base = (size_t)row * 2048 + d;
    float acc = kf.w * v[base];                           // w=3 -> v[t]
    if (t >= 1) acc += kf.z * v[base - 2048];             // w=2 -> v[t-1]
    if (t >= 2) acc += kf.y * v[base - 4096];             // w=1 -> v[t-2]
    if (t >= 3) acc += kf.x * v[base - 6144];             // w=0 -> v[t-3]
    v2[base] = acc * sigmoidf_(acc);
}

// ---------------------------------------------------------------------------
// beta = sigmoid(x@Wb), decay = exp(-exp(A_log)*softplus(x@Wa + dt_bias))
// ---------------------------------------------------------------------------
__global__ void __launch_bounds__(256) betag_kernel(
    const float* __restrict__ x, const float* __restrict__ Wb, const float* __restrict__ Wa,
    const float* __restrict__ dtb, const float* __restrict__ Alog,
    float* __restrict__ beta, float* __restrict__ decay)
{
    __shared__ float xs[16][128];
    __shared__ float wbs[128 * 17];
    __shared__ float was[128 * 17];
    const int tid = threadIdx.x;
    const int myrow = tid >> 4, mycol = tid & 15;
    const int r0 = blockIdx.x * 16;
    float pb = 0.f, pa = 0.f;
    for (int ch = 0; ch < 16; ++ch) {
        __syncthreads();
#pragma unroll
        for (int j = 0; j < 8; ++j) {
            int lin = tid + j * 256;
            int rr = lin >> 7, cc = lin & 127;
            xs[rr][cc] = x[(size_t)(r0 + rr) * 2048 + ch * 128 + cc];
            int wi = lin >> 4, wc = lin & 15;
            wbs[wi * 17 + wc] = Wb[(size_t)ch * 2048 + lin];
            was[wi * 17 + wc] = Wa[(size_t)ch * 2048 + lin];
        }
        __syncthreads();
#pragma unroll 8
        for (int i = 0; i < 128; ++i) {
            float xv = xs[myrow][i];
            pb = fmaf(xv, wbs[i * 17 + mycol], pb);
            pa = fmaf(xv, was[i * 17 + mycol], pa);
        }
    }
    int row = r0 + myrow;
    beta[row * 16 + mycol] = 1.f / (1.f + expf(-pb));
    float z = pa + dtb[mycol];
    float sp = (z > 20.f) ? z : log1pf(expf(z));
    decay[row * 16 + mycol] = expf(-expf(Alog[mycol]) * sp);
}

// ---------------------------------------------------------------------------
// In-place L2 normalize q and k per (row, head) of 128
// ---------------------------------------------------------------------------
__global__ void __launch_bounds__(256) l2norm_kernel(float* __restrict__ q, float* __restrict__ k)
{
    int u = blockIdx.x * 8 + (threadIdx.x >> 5);
    int lane = threadIdx.x & 31;
    size_t base = (size_t)u * 128 + lane * 4;
    {
        float4 a = *(float4*)(q + base);
        float ss = a.x * a.x + a.y * a.y + a.z * a.z + a.w * a.w;
#pragma unroll
        for (int m = 16; m >= 1; m >>= 1) ss += __shfl_xor_sync(0xffffffffu, ss, m);
        float sc = 1.f / fmaxf(sqrtf(ss), 1e-12f);
        a.x *= sc; a.y *= sc; a.z *= sc; a.w *= sc;
        *(float4*)(q + base) = a;
    }
    {
        float4 a = *(float4*)(k + base);
        float ss = a.x * a.x + a.y * a.y + a.z * a.z + a.w * a.w;
#pragma unroll
        for (int m = 16; m >= 1; m >>= 1) ss += __shfl_xor_sync(0xffffffffu, ss, m);
        float sc = 1.f / fmaxf(sqrtf(ss), 1e-12f);
        a.x *= sc; a.y *= sc; a.z *= sc; a.w *= sc;
        *(float4*)(k + base) = a;
    }
}

// ---------------------------------------------------------------------------
// Gated delta rule recurrence (parallel over b,h and dv-blocks; see R0 notes)
// ---------------------------------------------------------------------------
__global__ void __launch_bounds__(256, 1) recur_kernel(
    const float* __restrict__ qn, const float* __restrict__ kn,
    const float* __restrict__ v, const float* __restrict__ decay,
    const float* __restrict__ beta, float* __restrict__ o)
{
    const int bx = blockIdx.x;
    const int bh = bx >> 2;
    const int dvblk = bx & 3;
    const int b = bh >> 4;
    const int h = bh & 15;
    const int tid = threadIdx.x;
    const int dkg = tid & 7;
    const int dvi = tid >> 3;

    __shared__ float qs[2][128];
    __shared__ float ks[2][128];
    __shared__ float vs[2][32];
    __shared__ float gb[2][2];

    const size_t row0 = (size_t)b * 2048;
    const float* qrow = qn + row0 * 2048 + h * 128;
    const float* krow = kn + row0 * 2048 + h * 128;
    const float* vrow = v + row0 * 2048 + h * 128 + dvblk * 32;
    const float* grow = decay + row0 * 16 + h;
    const float* brow = beta + row0 * 16 + h;
    float* orow = o + row0 * 2048 + h * 128 + dvblk * 32 + dvi;

    float S[16];
#pragma unroll
    for (int i = 0; i < 16; ++i) S[i] = 0.f;

    if (tid < 128) qs[0][tid] = qrow[tid];
    else           ks[0][tid - 128] = krow[tid - 128];
    if (tid < 32)  vs[0][tid] = vrow[tid];
    if (tid == 32) gb[0][0] = grow[0];
    if (tid == 33) gb[0][1] = brow[0];

    for (int t = 0; t < 2048; ++t) {
        __syncthreads();
        const int buf = t & 1;
        float pf = 0.f, pv = 0.f, pg = 0.f, pb = 0.f;
        const bool more = (t + 1) < 2048;
        if (more) {
            size_t off = (size_t)(t + 1) * 2048;
            pf = (tid < 128) ? qrow[off + tid] : krow[off + tid - 128];
            if (tid < 32)  pv = vrow[off + tid];
            if (tid == 32) pg = grow[(size_t)(t + 1) * 16];
            if (tid == 33) pb = brow[(size_t)(t + 1) * 16];
        }
        float qv[16], kv[16];
#pragma unroll
        for (int j = 0; j < 4; ++j) {
            float4 a = *(const float4*)&qs[buf][dkg * 16 + j * 4];
            qv[j * 4 + 0] = a.x; qv[j * 4 + 1] = a.y; qv[j * 4 + 2] = a.z; qv[j * 4 + 3] = a.w;
            float4 c = *(const float4*)&ks[buf][dkg * 16 + j * 4];
            kv[j * 4 + 0] = c.x; kv[j * 4 + 1] = c.y; kv[j * 4 + 2] = c.z; kv[j * 4 + 3] = c.w;
        }
        float o0 = 0.f, o1 = 0.f, s0 = 0.f, s1 = 0.f;
#pragma unroll
        for (int i = 0; i < 16; i += 2) {
            o0 = fmaf(S[i],     qv[i],     o0);
            o1 = fmaf(S[i + 1], qv[i + 1], o1);
            s0 = fmaf(S[i],     kv[i],     s0);
            s1 = fmaf(S[i + 1], kv[i + 1], s1);
        }
        float ot = o0 + o1, sk = s0 + s1;
#pragma unroll
        for (int m = 4; m >= 1; m >>= 1) {
            ot += __shfl_xor_sync(0xffffffffu, ot, m);
            sk += __shfl_xor_sync(0xffffffffu, sk, m);
        }
        const float gt = gb[buf][0];
        const float bt = gb[buf][1];
        const float vt = vs[buf][dvi];
        const float cc = bt * (vt - sk);
#pragma unroll
        for (int i = 0; i < 16; ++i)
            S[i] = fmaf(cc, kv[i], S[i] * gt);
        if (dkg == 0) orow[(size_t)t * 2048] = ot;
        if (more) {
            const int nb = buf ^ 1;
            if (tid < 128) qs[nb][tid] = pf;
            else           ks[nb][tid - 128] = pf;
            if (tid < 32)  vs[nb][tid] = pv;
            if (tid == 32) gb[nb][0] = pg;
            if (tid == 33) gb[nb][1] = pb;
        }
    }
}

// ---------------------------------------------------------------------------
// Gated RMSNorm: og = (o * rsqrt(mean(o^2)+eps)) * nw * silu(gate)
// ---------------------------------------------------------------------------
__global__ void __launch_bounds__(256) rmsgate_kernel(
    const float* __restrict__ o, const float* __restrict__ xg,
    const float* __restrict__ nw, float* __restrict__ og)
{
    int u = blockIdx.x * 8 + (threadIdx.x >> 5);
    int lane = threadIdx.x & 31;
    size_t base = (size_t)u * 128 + lane * 4;
    float4 a = *(const float4*)(o + base);
    float ss = a.x * a.x + a.y * a.y + a.z * a.z + a.w * a.w;
#pragma unroll
    for (int m = 16; m >= 1; m >>= 1) ss += __shfl_xor_sync(0xffffffffu, ss, m);
    float r = rsqrtf(ss * (1.f / 128.f) + 1e-6f);
    float4 g = *(const float4*)(xg + base);
    float4 w = *(const float4*)(nw + lane * 4);
    float4 out;
    out.x = a.x * r * w.x * (g.x * sigmoidf_(g.x));
    out.y = a.y * r * w.y * (g.y * sigmoidf_(g.y));
    out.z = a.z * r * w.z * (g.z * sigmoidf_(g.z));
    out.w = a.w * r * w.w * (g.w * sigmoidf_(g.w));
    *(float4*)(og + base) = out;
}

// ---------------------------------------------------------------------------
extern "C" void kernel_launch(void* const* d_in, const int* in_sizes, int n_in,
                              void* d_out, int out_size)
{
    const float* x    = (const float*)d_in[0];
    const float* Wq   = (const float*)d_in[1];
    const float* Wk   = (const float*)d_in[2];
    const float* Wv   = (const float*)d_in[3];
    const float* Wb   = (const float*)d_in[4];
    const float* Wa   = (const float*)d_in[5];
    const float* dtb  = (const float*)d_in[6];
    const float* Alog = (const float*)d_in[7];
    const float* W1   = (const float*)d_in[8];
    const float* W2   = (const float*)d_in[9];
    const float* b2   = (const float*)d_in[10];
    const float* nw   = (const float*)d_in[11];
    const float* Wg   = (const float*)d_in[12];
    const float* Wo   = (const float*)d_in[13];
    float* out = (float*)d_out;

    float *q, *k, *v, *v2, *hpre, *kern, *o, *beta, *decay;
    cudaGetSymbolAddress((void**)&q,     g_q);
    cudaGetSymbolAddress((void**)&k,     g_k);
    cudaGetSymbolAddress((void**)&v,     g_v);
    cudaGetSymbolAddress((void**)&v2,    g_v2);
    cudaGetSymbolAddress((void**)&hpre,  g_hpre);
    cudaGetSymbolAddress((void**)&kern,  g_kern);
    cudaGetSymbolAddress((void**)&o,     g_o);
    cudaGetSymbolAddress((void**)&beta,  g_beta);
    cudaGetSymbolAddress((void**)&decay, g_decay);

    dim3 g16(16, 32);   // N=2048, M=4096
    dim3 g64(64, 32);   // N=8192, M=4096

    // projections
    gemm_kernel<0><<<g16, 256>>>(x, Wq, q, nullptr, 4096, 2048, 2048);
    gemm_kernel<0><<<g16, 256>>>(x, Wk, k, nullptr, 4096, 2048, 2048);
    gemm_kernel<0><<<g16, 256>>>(x, Wv, v, nullptr, 4096, 2048, 2048);
    // kernel generator: gi = concat(q,k); split into two accumulating passes
    gemm_kernel<0><<<g16, 256>>>(q, W1,                 hpre, nullptr, 4096, 2048, 2048);
    gemm_kernel<1><<<g16, 256>>>(k, W1 + 2048ll * 2048, hpre, nullptr, 4096, 2048, 2048); // +=, then SiLU
    gemm_kernel<2><<<g64, 256>>>(hpre, W2, kern, b2, 4096, 8192, 2048);                   // + bias
    // dynamic conv + SiLU
    conv_kernel<<<32768, 256>>>(kern, v, v2);
    // gating params
    betag_kernel<<<256, 256>>>(x, Wb, Wa, dtb, Alog, beta, decay);
    // L2 normalize q,k in place (gi passes already consumed raw q,k)
    l2norm_kernel<<<8192, 256>>>(q, k);
    // sequential recurrence (parallel over b,h,dv)
    recur_kernel<<<128, 256>>>(q, k, v2, decay, beta, o);
    // gate projection (reuse kern buffer as xg)
    gemm_kernel<0><<<g16, 256>>>(x, Wg, kern, nullptr, 4096, 2048, 2048);
    // gated RMSNorm (og into hpre buffer)
    rmsgate_kernel<<<8192, 256>>>(o, kern, nw, hpre);
    // output projection
    gemm_kernel<0><<<g16, 256>>>(hpre, Wo, out, nullptr, 4096, 2048, 2048);
}

// round 3
// speedup vs baseline: 1.3048x; 1.3048x over previous
#include <cuda_runtime.h>
#include <cuda_bf16.h>
#include <mma.h>

using namespace nvcuda;

// ---------------------------------------------------------------------------
// Dims (fixed): B=2, T=2048, HID=2048, H=16, DK=DV=128, W=4; rows = B*T = 4096
// ---------------------------------------------------------------------------

// Scratch (device globals; allocation in kernel_launch is forbidden)
__device__ float g_q   [4096ll * 2048];   // q (then qn in-place)
__device__ float g_k   [4096ll * 2048];   // k (then kn in-place)
__device__ float g_v   [4096ll * 2048];   // v = x@Wv
__device__ float g_v2  [4096ll * 2048];   // h1 = k@W1b, then silu(conv(v))
__device__ float g_hpre[4096ll * 2048];   // h0 = q@W1a, then og
__device__ float g_kern[4096ll * 8192];   // conv kernels
__device__ float g_o   [4096ll * 2048];   // recurrence output
__device__ float g_xg  [4096ll * 2048];   // gate projection
__device__ float g_beta [4096 * 16];
__device__ float g_decay[4096 * 16];

__device__ __forceinline__ float sigmoidf_(float x) { return 1.f / (1.f + expf(-x)); }

// Split one fp32 into bf16 hi + bf16 lo (lo = round(x - hi)); ~16-bit mantissa total.
__device__ __forceinline__ void split_pair(float x, float y,
                                           __nv_bfloat162& hi, __nv_bfloat162& lo)
{
    __nv_bfloat16 hx = __float2bfloat16_rn(x);
    __nv_bfloat16 hy = __float2bfloat16_rn(y);
    __nv_bfloat16 lx = __float2bfloat16_rn(x - __bfloat162float(hx));
    __nv_bfloat16 ly = __float2bfloat16_rn(y - __bfloat162float(hy));
    hi = __nv_bfloat162(hx, hy);
    lo = __nv_bfloat162(lx, ly);
}

struct GemmBatch {
    const float* A[4];
    const float* B[4];
    float*       C[4];
};

// ---------------------------------------------------------------------------
// Split-bf16 wmma GEMM: C[M,N] = A[M,K] @ B[K,N].
// acc += Ah*Bh + Ah*Bl + Al*Bh (fp32 accum). 3 MMAs -> ~2^-17 input precision.
// AMODE 0: A = bt.A[z].  AMODE 1: A = silu(A0 + A1) elementwise (fused gen1
// combine; A0 = bt.A[z], A1 = extra arg).
// CTA 128x128, K-tile 16, double-buffered dynamic smem, 8 warps (2x4),
// warp tile 64x32 (4x2 16x16 frags). 2 CTAs/SM (128 regs).
// Epilogue: direct fragment stores to global (no smem staging, no bias/act).
// ---------------------------------------------------------------------------
template <int AMODE>
__global__ void __launch_bounds__(256, 2) gemm_kernel(
    GemmBatch bt, const float* __restrict__ A1ptr, int M, int N, int K)
{
    extern __shared__ __align__(16) char smem_raw[];
    // per stage (20992 B): Ah(128x24 bf16)=6144, Al=6144, Bh(16x136)=4352, Bl=4352
    const int tid = threadIdx.x;
    const int wid = tid >> 5;
    const int wm  = wid >> 2;   // 0..1
    const int wn  = wid & 3;    // 0..3
    const int m0  = blockIdx.y << 7;
    const int n0  = blockIdx.x << 7;
    const float* __restrict__ A  = bt.A[blockIdx.z];
    const float* __restrict__ Bm = bt.B[blockIdx.z];
    float* __restrict__ C        = bt.C[blockIdx.z];

    auto Ah = [&](int s) -> __nv_bfloat16* { return (__nv_bfloat16*)(smem_raw + s * 20992); };
    auto Al = [&](int s) -> __nv_bfloat16* { return (__nv_bfloat16*)(smem_raw + s * 20992 + 6144); };
    auto Bh = [&](int s) -> __nv_bfloat16* { return (__nv_bfloat16*)(smem_raw + s * 20992 + 12288); };
    auto Bl = [&](int s) -> __nv_bfloat16* { return (__nv_bfloat16*)(smem_raw + s * 20992 + 16640); };

    wmma::fragment<wmma::accumulator, 16, 16, 16, float> acc[4][2];
#pragma unroll
    for (int i = 0; i < 4; ++i)
#pragma unroll
        for (int j = 0; j < 2; ++j) wmma::fill_fragment(acc[i][j], 0.f);

    // A-row/col for this thread's two A-load slots; B likewise
    auto tile_load = [&](int kt, float4 (&ra)[2], float4 (&rb)[2]) {
#pragma unroll
        for (int j = 0; j < 2; ++j) {
            int lin = tid + j * 256;
            int r = lin >> 2, c = (lin & 3) << 2;       // A: 128 x 16
            size_t gi = (size_t)(m0 + r) * K + kt * 16 + c;
            if (AMODE == 1) {
                float4 a0 = *(const float4*)(A + gi);
                float4 a1 = *(const float4*)(A1ptr + gi);
                float sx = a0.x + a1.x, sy = a0.y + a1.y;
                float sz = a0.z + a1.z, sw = a0.w + a1.w;
                ra[j].x = sx * sigmoidf_(sx);
                ra[j].y = sy * sigmoidf_(sy);
                ra[j].z = sz * sigmoidf_(sz);
                ra[j].w = sw * sigmoidf_(sw);
            } else {
                ra[j] = *(const float4*)(A + gi);
            }
        }
        const float* Bg = Bm + (size_t)kt * 16 * N + n0;
#pragma unroll
        for (int j = 0; j < 2; ++j) {
            int lin = tid + j * 256;
            int r = lin >> 5, c = (lin & 31) << 2;      // B: 16 x 128
            rb[j] = *(const float4*)(Bg + (size_t)r * N + c);
        }
    };
    auto stage_store = [&](int s, const float4 (&ra)[2], const float4 (&rb)[2]) {
        __nv_bfloat16* ah = Ah(s); __nv_bfloat16* al = Al(s);
        __nv_bfloat16* bh = Bh(s); __nv_bfloat16* bl = Bl(s);
#pragma unroll
        for (int j = 0; j < 2; ++j) {
            int lin = tid + j * 256;
            int r = lin >> 2, c = (lin & 3) << 2;
            __nv_bfloat162 h0, l0, h1, l1;
            split_pair(ra[j].x, ra[j].y, h0, l0);
            split_pair(ra[j].z, ra[j].w, h1, l1);
            *(__nv_bfloat162*)(ah + r * 24 + c)     = h0;
            *(__nv_bfloat162*)(ah + r * 24 + c + 2) = h1;
            *(__nv_bfloat162*)(al + r * 24 + c)     = l0;
            *(__nv_bfloat162*)(al + r * 24 + c + 2) = l1;
        }
#pragma unroll
        for (int j = 0; j < 2; ++j) {
            int lin = tid + j * 256;
            int r = lin >> 5, c = (lin & 31) << 2;
            __nv_bfloat162 h0, l0, h1, l1;
            split_pair(rb[j].x, rb[j].y, h0, l0);
            split_pair(rb[j].z, rb[j].w, h1, l1);
            *(__nv_bfloat162*)(bh + r * 136 + c)     = h0;
            *(__nv_bfloat162*)(bh + r * 136 + c + 2) = h1;
            *(__nv_bfloat162*)(bl + r * 136 + c)     = l0;
            *(__nv_bfloat162*)(bl + r * 136 + c + 2) = l1;
        }
    };

    // prologue
    {
        float4 ra[2], rb[2];
        tile_load(0, ra, rb);
        stage_store(0, ra, rb);
    }
    __syncthreads();

    const int KT = K >> 4;
    float4 ra[2], rb[2];
    for (int kt = 0; kt < KT; ++kt) {
        const int s = kt & 1;
        const bool more = (kt + 1) < KT;
        if (more) tile_load(kt + 1, ra, rb);

        __nv_bfloat16* ah = Ah(s); __nv_bfloat16* al = Al(s);
        __nv_bfloat16* bh = Bh(s); __nv_bfloat16* bl = Bl(s);

        wmma::fragment<wmma::matrix_b, 16, 16, 16, __nv_bfloat16, wmma::row_major> bfh[2], bfl[2];
#pragma unroll
        for (int ni = 0; ni < 2; ++ni) {
            wmma::load_matrix_sync(bfh[ni], bh + wn * 32 + ni * 16, 136);
            wmma::load_matrix_sync(bfl[ni], bl + wn * 32 + ni * 16, 136);
        }
#pragma unroll
        for (int mi = 0; mi < 4; ++mi) {
            wmma::fragment<wmma::matrix_a, 16, 16, 16, __nv_bfloat16, wmma::row_major> afh, afl;
            wmma::load_matrix_sync(afh, ah + (wm * 64 + mi * 16) * 24, 24);
            wmma::load_matrix_sync(afl, al + (wm * 64 + mi * 16) * 24, 24);
#pragma unroll
            for (int ni = 0; ni < 2; ++ni) {
                wmma::mma_sync(acc[mi][ni], afh, bfl[ni], acc[mi][ni]);
                wmma::mma_sync(acc[mi][ni], afl, bfh[ni], acc[mi][ni]);
                wmma::mma_sync(acc[mi][ni], afh, bfh[ni], acc[mi][ni]);
            }
        }

        if (more) {
            stage_store(s ^ 1, ra, rb);
            __syncthreads();
        }
    }

    // direct epilogue: fragment stores straight to global
#pragma unroll
    for (int mi = 0; mi < 4; ++mi)
#pragma unroll
        for (int ni = 0; ni < 2; ++ni)
            wmma::store_matrix_sync(C + (size_t)(m0 + wm * 64 + mi * 16) * N + n0 + wn * 32 + ni * 16,
                                    acc[mi][ni], N, wmma::mem_row_major);
}

// ---------------------------------------------------------------------------
// Dynamic short conv (W=4, causal) + bias on kernels + SiLU.
// kern: [rows, 2048, 4] (pre-bias), b2: [8192], v: [rows, 2048]
// ---------------------------------------------------------------------------
__global__ void __launch_bounds__(256) conv_kernel(
    const float* __restrict__ kern, const float* __restrict__ b2,
    const float* __restrict__ v, float* __restrict__ v2)
{
    int idx = blockIdx.x * 256 + threadIdx.x;   // rows*2048 threads
    int row = idx >> 11;
    int d   = idx & 2047;
    int t   = row & 2047;                       // T = 2048
    float4 kf = *(const float4*)(kern + (size_t)row * 8192 + d * 4);
    float4 bv = *(const float4*)(b2 + d * 4);
    kf.x += bv.x; kf.y += bv.y; kf.z += bv.z; kf.w += bv.w;
    size_t base = (size_t)row * 2048 + d;
    float acc = kf.w * v[base];                           // w=3 -> v[t]
    if (t >= 1) acc += kf.z * v[base - 2048];             // w=2 -> v[t-1]
    if (t >= 2) acc += kf.y * v[base - 4096];             // w=1 -> v[t-2]
    if (t >= 3) acc += kf.x * v[base - 6144];             // w=0 -> v[t-3]
    v2[base] = acc * sigmoidf_(acc);
}

// ---------------------------------------------------------------------------
// beta = sigmoid(x@Wb), decay = exp(-exp(A_log)*softplus(x@Wa + dt_bias))
// ---------------------------------------------------------------------------
__global__ void __launch_bounds__(256) betag_kernel(
    const float* __restrict__ x, const float* __restrict__ Wb, const float* __restrict__ Wa,
    const float* __restrict__ dtb, const float* __restrict__ Alog,
    float* __restrict__ beta, float* __restrict__ decay)
{
    __shared__ float xs[16][128];
    __shared__ float wbs[128 * 17];
    __shared__ float was[128 * 17];
    const int tid = threadIdx.x;
    const int myrow = tid >> 4, mycol = tid & 15;
    const int r0 = blockIdx.x * 16;
    float pb = 0.f, pa = 0.f;
    for (int ch = 0; ch < 16; ++ch) {
        __syncthreads();
#pragma unroll
        for (int j = 0; j < 8; ++j) {
            int lin = tid + j * 256;
            int rr = lin >> 7, cc = lin & 127;
            xs[rr][cc] = x[(size_t)(r0 + rr) * 2048 + ch * 128 + cc];
            int wi = lin >> 4, wc = lin & 15;
            wbs[wi * 17 + wc] = Wb[(size_t)ch * 2048 + lin];
            was[wi * 17 + wc] = Wa[(size_t)ch * 2048 + lin];
        }
        __syncthreads();
#pragma unroll 8
        for (int i = 0; i < 128; ++i) {
            float xv = xs[myrow][i];
            pb = fmaf(xv, wbs[i * 17 + mycol], pb);
            pa = fmaf(xv, was[i * 17 + mycol], pa);
        }
    }
    int row = r0 + myrow;
    beta[row * 16 + mycol] = 1.f / (1.f + expf(-pb));
    float z = pa + dtb[mycol];
    float sp = (z > 20.f) ? z : log1pf(expf(z));
    decay[row * 16 + mycol] = expf(-expf(Alog[mycol]) * sp);
}

// ---------------------------------------------------------------------------
// In-place L2 normalize q and k per (row, head) of 128
// ---------------------------------------------------------------------------
__global__ void __launch_bounds__(256) l2norm_kernel(float* __restrict__ q, float* __restrict__ k)
{
    int u = blockIdx.x * 8 + (threadIdx.x >> 5);
    int lane = threadIdx.x & 31;
    size_t base = (size_t)u * 128 + lane * 4;
    {
        float4 a = *(float4*)(q + base);
        float ss = a.x * a.x + a.y * a.y + a.z * a.z + a.w * a.w;
#pragma unroll
        for (int m = 16; m >= 1; m >>= 1) ss += __shfl_xor_sync(0xffffffffu, ss, m);
        float sc = 1.f / fmaxf(sqrtf(ss), 1e-12f);
        a.x *= sc; a.y *= sc; a.z *= sc; a.w *= sc;
        *(float4*)(q + base) = a;
    }
    {
        float4 a = *(float4*)(k + base);
        float ss = a.x * a.x + a.y * a.y + a.z * a.z + a.w * a.w;
#pragma unroll
        for (int m = 16; m >= 1; m >>= 1) ss += __shfl_xor_sync(0xffffffffu, ss, m);
        float sc = 1.f / fmaxf(sqrtf(ss), 1e-12f);
        a.x *= sc; a.y *= sc; a.z *= sc; a.w *= sc;
        *(float4*)(k + base) = a;
    }
}

// ---------------------------------------------------------------------------
// Gated delta rule recurrence (parallel over b,h and dv-blocks of 32)
// ---------------------------------------------------------------------------
__global__ void __launch_bounds__(256, 1) recur_kernel(
    const float* __restrict__ qn, const float* __restrict__ kn,
    const float* __restrict__ v, const float* __restrict__ decay,
    const float* __restrict__ beta, float* __restrict__ o)
{
    const int bx = blockIdx.x;
    const int bh = bx >> 2;
    const int dvblk = bx & 3;
    const int b = bh >> 4;
    const int h = bh & 15;
    const int tid = threadIdx.x;
    const int dkg = tid & 7;
    const int dvi = tid >> 3;

    __shared__ float qs[2][128];
    __shared__ float ks[2][128];
    __shared__ float vs[2][32];
    __shared__ float gb[2][2];

    const size_t row0 = (size_t)b * 2048;
    const float* qrow = qn + row0 * 2048 + h * 128;
    const float* krow = kn + row0 * 2048 + h * 128;
    const float* vrow = v + row0 * 2048 + h * 128 + dvblk * 32;
    const float* grow = decay + row0 * 16 + h;
    const float* brow = beta + row0 * 16 + h;
    float* orow = o + row0 * 2048 + h * 128 + dvblk * 32 + dvi;

    float S[16];
#pragma unroll
    for (int i = 0; i < 16; ++i) S[i] = 0.f;

    if (tid < 128) qs[0][tid] = qrow[tid];
    else           ks[0][tid - 128] = krow[tid - 128];
    if (tid < 32)  vs[0][tid] = vrow[tid];
    if (tid == 32) gb[0][0] = grow[0];
    if (tid == 33) gb[0][1] = brow[0];

    for (int t = 0; t < 2048; ++t) {
        __syncthreads();
        const int buf = t & 1;
        float pf = 0.f, pv = 0.f, pg = 0.f, pb = 0.f;
        const bool more = (t + 1) < 2048;
        if (more) {
            size_t off = (size_t)(t + 1) * 2048;
            pf = (tid < 128) ? qrow[off + tid] : krow[off + tid - 128];
            if (tid < 32)  pv = vrow[off + tid];
            if (tid == 32) pg = grow[(size_t)(t + 1) * 16];
            if (tid == 33) pb = brow[(size_t)(t + 1) * 16];
        }
        float qv[16], kv[16];
#pragma unroll
        for (int j = 0; j < 4; ++j) {
            float4 a = *(const float4*)&qs[buf][dkg * 16 + j * 4];
            qv[j * 4 + 0] = a.x; qv[j * 4 + 1] = a.y; qv[j * 4 + 2] = a.z; qv[j * 4 + 3] = a.w;
            float4 c = *(const float4*)&ks[buf][dkg * 16 + j * 4];
            kv[j * 4 + 0] = c.x; kv[j * 4 + 1] = c.y; kv[j * 4 + 2] = c.z; kv[j * 4 + 3] = c.w;
        }
        float o0 = 0.f, o1 = 0.f, s0 = 0.f, s1 = 0.f;
#pragma unroll
        for (int i = 0; i < 16; i += 2) {
            o0 = fmaf(S[i],     qv[i],     o0);
            o1 = fmaf(S[i + 1], qv[i + 1], o1);
            s0 = fmaf(S[i],     kv[i],     s0);
            s1 = fmaf(S[i + 1], kv[i + 1], s1);
        }
        float ot = o0 + o1, sk = s0 + s1;
#pragma unroll
        for (int m = 4; m >= 1; m >>= 1) {
            ot += __shfl_xor_sync(0xffffffffu, ot, m);
            sk += __shfl_xor_sync(0xffffffffu, sk, m);
        }
        const float gt = gb[buf][0];
        const float bt = gb[buf][1];
        const float vt = vs[buf][dvi];
        const float cc = bt * (vt - sk);
#pragma unroll
        for (int i = 0; i < 16; ++i)
            S[i] = fmaf(cc, kv[i], S[i] * gt);
        if (dkg == 0) orow[(size_t)t * 2048] = ot;
        if (more) {
            const int nb = buf ^ 1;
            if (tid < 128) qs[nb][tid] = pf;
            else           ks[nb][tid - 128] = pf;
            if (tid < 32)  vs[nb][tid] = pv;
            if (tid == 32) gb[nb][0] = pg;
            if (tid == 33) gb[nb][1] = pb;
        }
    }
}

// ---------------------------------------------------------------------------
// Gated RMSNorm: og = (o * rsqrt(mean(o^2)+eps)) * nw * silu(gate)
// ---------------------------------------------------------------------------
__global__ void __launch_bounds__(256) rmsgate_kernel(
    const float* __restrict__ o, const float* __restrict__ xg,
    const float* __restrict__ nw, float* __restrict__ og)
{
    int u = blockIdx.x * 8 + (threadIdx.x >> 5);
    int lane = threadIdx.x & 31;
    size_t base = (size_t)u * 128 + lane * 4;
    float4 a = *(const float4*)(o + base);
    float ss = a.x * a.x + a.y * a.y + a.z * a.z + a.w * a.w;
#pragma unroll
    for (int m = 16; m >= 1; m >>= 1) ss += __shfl_xor_sync(0xffffffffu, ss, m);
    float r = rsqrtf(ss * (1.f / 128.f) + 1e-6f);
    float4 g = *(const float4*)(xg + base);
    float4 w = *(const float4*)(nw + lane * 4);
    float4 out;
    out.x = a.x * r * w.x * (g.x * sigmoidf_(g.x));
    out.y = a.y * r * w.y * (g.y * sigmoidf_(g.y));
    out.z = a.z * r * w.z * (g.z * sigmoidf_(g.z));
    out.w = a.w * r * w.w * (g.w * sigmoidf_(g.w));
    *(float4*)(og + base) = out;
}

// ---------------------------------------------------------------------------
extern "C" void kernel_launch(void* const* d_in, const int* in_sizes, int n_in,
                              void* d_out, int out_size)
{
    const float* x    = (const float*)d_in[0];
    const float* Wq   = (const float*)d_in[1];
    const float* Wk   = (const float*)d_in[2];
    const float* Wv   = (const float*)d_in[3];
    const float* Wb   = (const float*)d_in[4];
    const float* Wa   = (const float*)d_in[5];
    const float* dtb  = (const float*)d_in[6];
    const float* Alog = (const float*)d_in[7];
    const float* W1   = (const float*)d_in[8];
    const float* W2   = (const float*)d_in[9];
    const float* b2   = (const float*)d_in[10];
    const float* nw   = (const float*)d_in[11];
    const float* Wg   = (const float*)d_in[12];
    const float* Wo   = (const float*)d_in[13];
    float* out = (float*)d_out;

    float *q, *k, *v, *v2, *hpre, *kern, *o, *xg, *beta, *decay;
    cudaGetSymbolAddress((void**)&q,     g_q);
    cudaGetSymbolAddress((void**)&k,     g_k);
    cudaGetSymbolAddress((void**)&v,     g_v);
    cudaGetSymbolAddress((void**)&v2,    g_v2);
    cudaGetSymbolAddress((void**)&hpre,  g_hpre);
    cudaGetSymbolAddress((void**)&kern,  g_kern);
    cudaGetSymbolAddress((void**)&o,     g_o);
    cudaGetSymbolAddress((void**)&xg,    g_xg);
    cudaGetSymbolAddress((void**)&beta,  g_beta);
    cudaGetSymbolAddress((void**)&decay, g_decay);

    const int SMEM = 41984;

    // 1) fused projections: q,k,v,xg = x @ {Wq,Wk,Wv,Wg}   (2048 CTAs)
    {
        GemmBatch bt{};
        bt.A[0] = x;  bt.A[1] = x;  bt.A[2] = x;  bt.A[3] = x;
        bt.B[0] = Wq; bt.B[1] = Wk; bt.B[2] = Wv; bt.B[3] = Wg;
        bt.C[0] = q;  bt.C[1] = k;  bt.C[2] = v;  bt.C[3] = xg;
        gemm_kernel<0><<<dim3(16, 32, 4), 256, SMEM>>>(bt, nullptr, 4096, 2048, 2048);
    }
    // 2) generator layer 1 halves: h0 = q@W1[:2048], h1 = k@W1[2048:]  (1024 CTAs)
    {
        GemmBatch bt{};
        bt.A[0] = q;  bt.A[1] = k;
        bt.B[0] = W1; bt.B[1] = W1 + 2048ll * 2048;
        bt.C[0] = hpre; bt.C[1] = v2;
        gemm_kernel<0><<<dim3(16, 32, 2), 256, SMEM>>>(bt, nullptr, 4096, 2048, 2048);
    }
    // 3) generator layer 2 with fused silu(h0+h1) on the A path (bias folded into conv)
    {
        GemmBatch bt{};
        bt.A[0] = hpre; bt.B[0] = W2; bt.C[0] = kern;
        gemm_kernel<1><<<dim3(64, 32, 1), 256, SMEM>>>(bt, v2, 4096, 8192, 2048);
    }
    // 4) dynamic conv (+gen_b2) + SiLU  (v2 is free again after step 3)
    conv_kernel<<<32768, 256>>>(kern, b2, v, v2);
    // 5) gating params
    betag_kernel<<<256, 256>>>(x, Wb, Wa, dtb, Alog, beta, decay);
    // 6) L2 normalize q,k in place (generator already consumed raw q,k)
    l2norm_kernel<<<8192, 256>>>(q, k);
    // 7) sequential recurrence (parallel over b,h,dv)
    recur_kernel<<<128, 256>>>(q, k, v2, decay, beta, o);
    // 8) gated RMSNorm -> og (reuse hpre)
    rmsgate_kernel<<<8192, 256>>>(o, xg, nw, hpre);
    // 9) output projection
    {
        GemmBatch bt{};
        bt.A[0] = hpre; bt.B[0] = Wo; bt.C[0] = out;
        gemm_kernel<0><<<dim3(16, 32, 1), 256, SMEM>>>(bt, nullptr, 4096, 2048, 2048);
    }
}

// round 5
// speedup vs baseline: 1.6272x; 1.2471x over previous
#include <cuda_runtime.h>
#include <cuda_bf16.h>
#include <mma.h>
#include <cstdint>

using namespace nvcuda;

// ---------------------------------------------------------------------------
// Dims (fixed): B=2, T=2048, HID=2048, H=16, DK=DV=128, W=4; rows = B*T = 4096
// NOTE: this toolchain lowers to compute_103 PTX (no tcgen05/TMA-tensor).
// Stay on sm_80-portable PTX: cp.async + wmma(HMMA) + LDSM.
// ---------------------------------------------------------------------------

// Scratch (device globals; allocation in kernel_launch is forbidden)
__device__ float g_q   [4096ll * 2048];
__device__ float g_k   [4096ll * 2048];
__device__ float g_v   [4096ll * 2048];
__device__ float g_v2  [4096ll * 2048];   // h1, then silu(conv(v))
__device__ float g_hpre[4096ll * 2048];   // h0, then og
__device__ float g_kern[4096ll * 8192];
__device__ float g_o   [4096ll * 2048];
__device__ float g_xg  [4096ll * 2048];
__device__ float g_beta [4096 * 16];
__device__ float g_decay[4096 * 16];

// Pre-transposed + split weights: [N, K=2048] bf16 hi/lo
#define MELEM 4194304ll
#define OFF_Q   (0ll)
#define OFF_K   (1ll * MELEM)
#define OFF_V   (2ll * MELEM)
#define OFF_G   (3ll * MELEM)
#define OFF_W1A (4ll * MELEM)
#define OFF_W1B (5ll * MELEM)
#define OFF_WO  (6ll * MELEM)
#define OFF_W2  (7ll * MELEM)
__device__ __nv_bfloat16 g_wth[11ll * MELEM];
__device__ __nv_bfloat16 g_wtl[11ll * MELEM];

// Split activation buffers (two ping-pong pairs), [4096, 2048] bf16
__device__ __nv_bfloat16 g_p0h[4096ll * 2048];
__device__ __nv_bfloat16 g_p0l[4096ll * 2048];
__device__ __nv_bfloat16 g_p1h[4096ll * 2048];
__device__ __nv_bfloat16 g_p1l[4096ll * 2048];

__device__ __forceinline__ float sigmoidf_(float x) { return 1.f / (1.f + expf(-x)); }

__device__ __forceinline__ uint32_t smem_u32(const void* p) {
    uint32_t a;
    asm("{ .reg .u64 t; cvta.to.shared.u64 t, %1; cvt.u32.u64 %0, t; }" : "=r"(a) : "l"(p));
    return a;
}
__device__ __forceinline__ void cp16(uint32_t so, const void* g) {
    asm volatile("cp.async.cg.shared.global [%0], [%1], 16;" :: "r"(so), "l"(g));
}

struct GB {
    const __nv_bfloat16* Ah[4];
    const __nv_bfloat16* Al[4];
    const __nv_bfloat16* Bh[4];
    const __nv_bfloat16* Bl[4];
    float*               C[4];
};

// ---------------------------------------------------------------------------
// Weight prep: transpose [K,N] fp32 -> [N,K] bf16 hi/lo split
// ---------------------------------------------------------------------------
struct PrepBatch { const float* W[7]; long long off[7]; };

__global__ void __launch_bounds__(256) prep_kernel(
    PrepBatch pb, __nv_bfloat16* __restrict__ Th, __nv_bfloat16* __restrict__ Tl, int N)
{
    __shared__ float s[32][33];
    const float* W = pb.W[blockIdx.z];
    const long long base = pb.off[blockIdx.z];
    const int n0 = blockIdx.x * 32, k0 = blockIdx.y * 32;
    const int tid = threadIdx.x;
#pragma unroll
    for (int j = 0; j < 4; ++j) {
        int lin = tid + j * 256;
        int kk = lin >> 5, nn = lin & 31;
        s[kk][nn] = W[(size_t)(k0 + kk) * N + n0 + nn];
    }
    __syncthreads();
#pragma unroll
    for (int j = 0; j < 4; ++j) {
        int lin = tid + j * 256;
        int nn = lin >> 5, kk = lin & 31;
        float v = s[kk][nn];
        __nv_bfloat16 h = __float2bfloat16_rn(v);
        __nv_bfloat16 l = __float2bfloat16_rn(v - __bfloat162float(h));
        size_t o = (size_t)base + (size_t)(n0 + nn) * 2048 + k0 + kk;
        Th[o] = h;
        Tl[o] = l;
    }
}

// ---------------------------------------------------------------------------
// Elementwise fp32 -> bf16 hi/lo split (8M elems), float4 path
// ---------------------------------------------------------------------------
__device__ __forceinline__ void split4_store(
    float4 v, __nv_bfloat16* __restrict__ h, __nv_bfloat16* __restrict__ l, size_t i)
{
    __nv_bfloat16 hx = __float2bfloat16_rn(v.x), hy = __float2bfloat16_rn(v.y);
    __nv_bfloat16 hz = __float2bfloat16_rn(v.z), hw = __float2bfloat16_rn(v.w);
    __nv_bfloat16 lx = __float2bfloat16_rn(v.x - __bfloat162float(hx));
    __nv_bfloat16 ly = __float2bfloat16_rn(v.y - __bfloat162float(hy));
    __nv_bfloat16 lz = __float2bfloat16_rn(v.z - __bfloat162float(hz));
    __nv_bfloat16 lw = __float2bfloat16_rn(v.w - __bfloat162float(hw));
    __nv_bfloat162 h0(hx, hy), h1(hz, hw), l0(lx, ly), l1(lz, lw);
    *(uint2*)(h + i) = make_uint2(*(uint32_t*)&h0, *(uint32_t*)&h1);
    *(uint2*)(l + i) = make_uint2(*(uint32_t*)&l0, *(uint32_t*)&l1);
}

__global__ void __launch_bounds__(256) split_kernel(
    const float* __restrict__ s, __nv_bfloat16* __restrict__ h, __nv_bfloat16* __restrict__ l)
{
    size_t i = ((size_t)blockIdx.x * 256 + threadIdx.x) * 4;
    split4_store(*(const float4*)(s + i), h, l, i);
}

__global__ void __launch_bounds__(256) silu_split_kernel(
    const float* __restrict__ a, const float* __restrict__ b,
    __nv_bfloat16* __restrict__ h, __nv_bfloat16* __restrict__ l)
{
    size_t i = ((size_t)blockIdx.x * 256 + threadIdx.x) * 4;
    float4 va = *(const float4*)(a + i);
    float4 vb = *(const float4*)(b + i);
    float4 v;
    float sx = va.x + vb.x, sy = va.y + vb.y, sz = va.z + vb.z, sw = va.w + vb.w;
    v.x = sx * sigmoidf_(sx);
    v.y = sy * sigmoidf_(sy);
    v.z = sz * sigmoidf_(sz);
    v.w = sw * sigmoidf_(sw);
    split4_store(v, h, l, i);
}

// ---------------------------------------------------------------------------
// Split-bf16 HMMA GEMM with cp.async pipeline.
// C[M,N] = (Ah+Al)[M,K] @ (Bh+Bl)[K,N], B stored K-major [N,K] (col_major frags).
// acc += Ah*Bh + Ah*Bl + Al*Bh (fp32). CTA 128x128, K-chunk 32, 2-stage.
// smem/stage 40KB: Ah +0, Al +10240, Bh +20480, Bl +30720 (row stride 80B).
// ---------------------------------------------------------------------------
__global__ void __launch_bounds__(256, 2) gemm_cp(
    GB bt, int M, int N, int K)
{
    extern __shared__ __align__(16) char dsm[];
    const int tid = threadIdx.x;
    const int wid = tid >> 5;
    const int wm  = wid >> 2;   // 0..1
    const int wn  = wid & 3;    // 0..3
    const int m0  = blockIdx.y << 7;
    const int n0  = blockIdx.x << 7;
    const __nv_bfloat16* __restrict__ Ah = bt.Ah[blockIdx.z];
    const __nv_bfloat16* __restrict__ Al = bt.Al[blockIdx.z];
    const __nv_bfloat16* __restrict__ Bh = bt.Bh[blockIdx.z];
    const __nv_bfloat16* __restrict__ Bl = bt.Bl[blockIdx.z];
    float* __restrict__ C = bt.C[blockIdx.z];

    const uint32_t sbase = smem_u32(dsm);
    // per-thread fixed copy slots (2 rows per matrix per thread)
    const int r0 = tid >> 2, c16 = tid & 3;          // row 0..63, 16B col 0..3
    const int r1 = r0 + 64;

    auto issue = [&](int s, int kc) {
        const uint32_t sb = sbase + s * 40960;
        const size_t ka = (size_t)kc * 32 + c16 * 8;
        {
            uint32_t so = sb + r0 * 80 + c16 * 16;
            cp16(so,         Ah + (size_t)(m0 + r0) * K + ka);
            cp16(so + 10240, Al + (size_t)(m0 + r0) * K + ka);
            cp16(so + 20480, Bh + (size_t)(n0 + r0) * K + ka);
            cp16(so + 30720, Bl + (size_t)(n0 + r0) * K + ka);
        }
        {
            uint32_t so = sb + r1 * 80 + c16 * 16;
            cp16(so,         Ah + (size_t)(m0 + r1) * K + ka);
            cp16(so + 10240, Al + (size_t)(m0 + r1) * K + ka);
            cp16(so + 20480, Bh + (size_t)(n0 + r1) * K + ka);
            cp16(so + 30720, Bl + (size_t)(n0 + r1) * K + ka);
        }
    };

    wmma::fragment<wmma::accumulator, 16, 16, 16, float> acc[4][2];
#pragma unroll
    for (int i = 0; i < 4; ++i)
#pragma unroll
        for (int j = 0; j < 2; ++j) wmma::fill_fragment(acc[i][j], 0.f);

    // prologue: chunk 0 -> buf 0
    issue(0, 0);
    asm volatile("cp.async.commit_group;");

    const int NC = K >> 5;
    for (int c = 0; c < NC; ++c) {
        const int s = c & 1;
        if (c + 1 < NC) issue(s ^ 1, c + 1);
        asm volatile("cp.async.commit_group;");      // may be empty; keeps group count uniform
        asm volatile("cp.async.wait_group 1;");
        __syncthreads();

        const __nv_bfloat16* ah = (const __nv_bfloat16*)(dsm + s * 40960);
        const __nv_bfloat16* al = (const __nv_bfloat16*)(dsm + s * 40960 + 10240);
        const __nv_bfloat16* bh = (const __nv_bfloat16*)(dsm + s * 40960 + 20480);
        const __nv_bfloat16* bl = (const __nv_bfloat16*)(dsm + s * 40960 + 30720);

#pragma unroll
        for (int kk = 0; kk < 2; ++kk) {
            wmma::fragment<wmma::matrix_b, 16, 16, 16, __nv_bfloat16, wmma::col_major> bfh[2], bfl[2];
#pragma unroll
            for (int ni = 0; ni < 2; ++ni) {
                wmma::load_matrix_sync(bfh[ni], bh + (wn * 32 + ni * 16) * 40 + kk * 16, 40);
                wmma::load_matrix_sync(bfl[ni], bl + (wn * 32 + ni * 16) * 40 + kk * 16, 40);
            }
#pragma unroll
            for (int mi = 0; mi < 4; ++mi) {
                wmma::fragment<wmma::matrix_a, 16, 16, 16, __nv_bfloat16, wmma::row_major> afh, afl;
                wmma::load_matrix_sync(afh, ah + (wm * 64 + mi * 16) * 40 + kk * 16, 40);
                wmma::load_matrix_sync(afl, al + (wm * 64 + mi * 16) * 40 + kk * 16, 40);
#pragma unroll
                for (int ni = 0; ni < 2; ++ni) {
                    wmma::mma_sync(acc[mi][ni], afh, bfl[ni], acc[mi][ni]);
                    wmma::mma_sync(acc[mi][ni], afl, bfh[ni], acc[mi][ni]);
                    wmma::mma_sync(acc[mi][ni], afh, bfh[ni], acc[mi][ni]);
                }
            }
        }
        __syncthreads();
    }

    // direct epilogue
#pragma unroll
    for (int mi = 0; mi < 4; ++mi)
#pragma unroll
        for (int ni = 0; ni < 2; ++ni)
            wmma::store_matrix_sync(C + (size_t)(m0 + wm * 64 + mi * 16) * N + n0 + wn * 32 + ni * 16,
                                    acc[mi][ni], N, wmma::mem_row_major);
}

// ---------------------------------------------------------------------------
// Dynamic short conv (W=4, causal) + bias on kernels + SiLU.
// ---------------------------------------------------------------------------
__global__ void __launch_bounds__(256) conv_kernel(
    const float* __restrict__ kern, const float* __restrict__ b2,
    const float* __restrict__ v, float* __restrict__ v2)
{
    int idx = blockIdx.x * 256 + threadIdx.x;
    int row = idx >> 11;
    int d   = idx & 2047;
    int t   = row & 2047;
    float4 kf = *(const float4*)(kern + (size_t)row * 8192 + d * 4);
    float4 bv = *(const float4*)(b2 + d * 4);
    kf.x += bv.x; kf.y += bv.y; kf.z += bv.z; kf.w += bv.w;
    size_t base = (size_t)row * 2048 + d;
    float acc = kf.w * v[base];
    if (t >= 1) acc += kf.z * v[base - 2048];
    if (t >= 2) acc += kf.y * v[base - 4096];
    if (t >= 3) acc += kf.x * v[base - 6144];
    v2[base] = acc * sigmoidf_(acc);
}

// ---------------------------------------------------------------------------
// beta = sigmoid(x@Wb), decay = exp(-exp(A_log)*softplus(x@Wa + dt_bias))
// ---------------------------------------------------------------------------
__global__ void __launch_bounds__(256) betag_kernel(
    const float* __restrict__ x, const float* __restrict__ Wb, const float* __restrict__ Wa,
    const float* __restrict__ dtb, const float* __restrict__ Alog,
    float* __restrict__ beta, float* __restrict__ decay)
{
    __shared__ float xs[16][128];
    __shared__ float wbs[128 * 17];
    __shared__ float was[128 * 17];
    const int tid = threadIdx.x;
    const int myrow = tid >> 4, mycol = tid & 15;
    const int r0 = blockIdx.x * 16;
    float pb = 0.f, pa = 0.f;
    for (int ch = 0; ch < 16; ++ch) {
        __syncthreads();
#pragma unroll
        for (int j = 0; j < 8; ++j) {
            int lin = tid + j * 256;
            int rr = lin >> 7, cc = lin & 127;
            xs[rr][cc] = x[(size_t)(r0 + rr) * 2048 + ch * 128 + cc];
            int wi = lin >> 4, wc = lin & 15;
            wbs[wi * 17 + wc] = Wb[(size_t)ch * 2048 + lin];
            was[wi * 17 + wc] = Wa[(size_t)ch * 2048 + lin];
        }
        __syncthreads();
#pragma unroll 8
        for (int i = 0; i < 128; ++i) {
            float xv = xs[myrow][i];
            pb = fmaf(xv, wbs[i * 17 + mycol], pb);
            pa = fmaf(xv, was[i * 17 + mycol], pa);
        }
    }
    int row = r0 + myrow;
    beta[row * 16 + mycol] = 1.f / (1.f + expf(-pb));
    float z = pa + dtb[mycol];
    float sp = (z > 20.f) ? z : log1pf(expf(z));
    decay[row * 16 + mycol] = expf(-expf(Alog[mycol]) * sp);
}

// ---------------------------------------------------------------------------
// In-place L2 normalize q and k per (row, head) of 128
// ---------------------------------------------------------------------------
__global__ void __launch_bounds__(256) l2norm_kernel(float* __restrict__ q, float* __restrict__ k)
{
    int u = blockIdx.x * 8 + (threadIdx.x >> 5);
    int lane = threadIdx.x & 31;
    size_t base = (size_t)u * 128 + lane * 4;
    {
        float4 a = *(float4*)(q + base);
        float ss = a.x * a.x + a.y * a.y + a.z * a.z + a.w * a.w;
#pragma unroll
        for (int m = 16; m >= 1; m >>= 1) ss += __shfl_xor_sync(0xffffffffu, ss, m);
        float sc = 1.f / fmaxf(sqrtf(ss), 1e-12f);
        a.x *= sc; a.y *= sc; a.z *= sc; a.w *= sc;
        *(float4*)(q + base) = a;
    }
    {
        float4 a = *(float4*)(k + base);
        float ss = a.x * a.x + a.y * a.y + a.z * a.z + a.w * a.w;
#pragma unroll
        for (int m = 16; m >= 1; m >>= 1) ss += __shfl_xor_sync(0xffffffffu, ss, m);
        float sc = 1.f / fmaxf(sqrtf(ss), 1e-12f);
        a.x *= sc; a.y *= sc; a.z *= sc; a.w *= sc;
        *(float4*)(k + base) = a;
    }
}

// ---------------------------------------------------------------------------
// Gated delta rule recurrence (parallel over b,h and dv-blocks of 32)
// ---------------------------------------------------------------------------
__global__ void __launch_bounds__(256, 1) recur_kernel(
    const float* __restrict__ qn, const float* __restrict__ kn,
    const float* __restrict__ v, const float* __restrict__ decay,
    const float* __restrict__ beta, float* __restrict__ o)
{
    const int bx = blockIdx.x;
    const int bh = bx >> 2;
    const int dvblk = bx & 3;
    const int b = bh >> 4;
    const int h = bh & 15;
    const int tid = threadIdx.x;
    const int dkg = tid & 7;
    const int dvi = tid >> 3;

    __shared__ float qs[2][128];
    __shared__ float ks[2][128];
    __shared__ float vs[2][32];
    __shared__ float gb[2][2];

    const size_t row0 = (size_t)b * 2048;
    const float* qrow = qn + row0 * 2048 + h * 128;
    const float* krow = kn + row0 * 2048 + h * 128;
    const float* vrow = v + row0 * 2048 + h * 128 + dvblk * 32;
    const float* grow = decay + row0 * 16 + h;
    const float* brow = beta + row0 * 16 + h;
    float* orow = o + row0 * 2048 + h * 128 + dvblk * 32 + dvi;

    float S[16];
#pragma unroll
    for (int i = 0; i < 16; ++i) S[i] = 0.f;

    if (tid < 128) qs[0][tid] = qrow[tid];
    else           ks[0][tid - 128] = krow[tid - 128];
    if (tid < 32)  vs[0][tid] = vrow[tid];
    if (tid == 32) gb[0][0] = grow[0];
    if (tid == 33) gb[0][1] = brow[0];

    for (int t = 0; t < 2048; ++t) {
        __syncthreads();
        const int buf = t & 1;
        float pf = 0.f, pv = 0.f, pg = 0.f, pb = 0.f;
        const bool more = (t + 1) < 2048;
        if (more) {
            size_t off = (size_t)(t + 1) * 2048;
            pf = (tid < 128) ? qrow[off + tid] : krow[off + tid - 128];
            if (tid < 32)  pv = vrow[off + tid];
            if (tid == 32) pg = grow[(size_t)(t + 1) * 16];
            if (tid == 33) pb = brow[(size_t)(t + 1) * 16];
        }
        float qv[16], kv[16];
#pragma unroll
        for (int j = 0; j < 4; ++j) {
            float4 a = *(const float4*)&qs[buf][dkg * 16 + j * 4];
            qv[j * 4 + 0] = a.x; qv[j * 4 + 1] = a.y; qv[j * 4 + 2] = a.z; qv[j * 4 + 3] = a.w;
            float4 c = *(const float4*)&ks[buf][dkg * 16 + j * 4];
            kv[j * 4 + 0] = c.x; kv[j * 4 + 1] = c.y; kv[j * 4 + 2] = c.z; kv[j * 4 + 3] = c.w;
        }
        float o0 = 0.f, o1 = 0.f, s0 = 0.f, s1 = 0.f;
#pragma unroll
        for (int i = 0; i < 16; i += 2) {
            o0 = fmaf(S[i],     qv[i],     o0);
            o1 = fmaf(S[i + 1], qv[i + 1], o1);
            s0 = fmaf(S[i],     kv[i],     s0);
            s1 = fmaf(S[i + 1], kv[i + 1], s1);
        }
        float ot = o0 + o1, sk = s0 + s1;
#pragma unroll
        for (int m = 4; m >= 1; m >>= 1) {
            ot += __shfl_xor_sync(0xffffffffu, ot, m);
            sk += __shfl_xor_sync(0xffffffffu, sk, m);
        }
        const float gt = gb[buf][0];
        const float bt = gb[buf][1];
        const float vt = vs[buf][dvi];
        const float cc = bt * (vt - sk);
#pragma unroll
        for (int i = 0; i < 16; ++i)
            S[i] = fmaf(cc, kv[i], S[i] * gt);
        if (dkg == 0) orow[(size_t)t * 2048] = ot;
        if (more) {
            const int nb = buf ^ 1;
            if (tid < 128) qs[nb][tid] = pf;
            else           ks[nb][tid - 128] = pf;
            if (tid < 32)  vs[nb][tid] = pv;
            if (tid == 32) gb[nb][0] = pg;
            if (tid == 33) gb[nb][1] = pb;
        }
    }
}

// ---------------------------------------------------------------------------
// Gated RMSNorm: og = (o * rsqrt(mean(o^2)+eps)) * nw * silu(gate)
// ---------------------------------------------------------------------------
__global__ void __launch_bounds__(256) rmsgate_kernel(
    const float* __restrict__ o, const float* __restrict__ xg,
    const float* __restrict__ nw, float* __restrict__ og)
{
    int u = blockIdx.x * 8 + (threadIdx.x >> 5);
    int lane = threadIdx.x & 31;
    size_t base = (size_t)u * 128 + lane * 4;
    float4 a = *(const float4*)(o + base);
    float ss = a.x * a.x + a.y * a.y + a.z * a.z + a.w * a.w;
#pragma unroll
    for (int m = 16; m >= 1; m >>= 1) ss += __shfl_xor_sync(0xffffffffu, ss, m);
    float r = rsqrtf(ss * (1.f / 128.f) + 1e-6f);
    float4 g = *(const float4*)(xg + base);
    float4 w = *(const float4*)(nw + lane * 4);
    float4 out;
    out.x = a.x * r * w.x * (g.x * sigmoidf_(g.x));
    out.y = a.y * r * w.y * (g.y * sigmoidf_(g.y));
    out.z = a.z * r * w.z * (g.z * sigmoidf_(g.z));
    out.w = a.w * r * w.w * (g.w * sigmoidf_(g.w));
    *(float4*)(og + base) = out;
}

// ---------------------------------------------------------------------------
extern "C" void kernel_launch(void* const* d_in, const int* in_sizes, int n_in,
                              void* d_out, int out_size)
{
    const float* x    = (const float*)d_in[0];
    const float* Wq   = (const float*)d_in[1];
    const float* Wk   = (const float*)d_in[2];
    const float* Wv   = (const float*)d_in[3];
    const float* Wb   = (const float*)d_in[4];
    const float* Wa   = (const float*)d_in[5];
    const float* dtb  = (const float*)d_in[6];
    const float* Alog = (const float*)d_in[7];
    const float* W1   = (const float*)d_in[8];
    const float* W2   = (const float*)d_in[9];
    const float* b2   = (const float*)d_in[10];
    const float* nw   = (const float*)d_in[11];
    const float* Wg   = (const float*)d_in[12];
    const float* Wo   = (const float*)d_in[13];
    float* out = (float*)d_out;

    float *q, *k, *v, *v2, *hpre, *kern, *o, *xg, *beta, *decay;
    __nv_bfloat16 *wth, *wtl, *p0h, *p0l, *p1h, *p1l;
    cudaGetSymbolAddress((void**)&q,     g_q);
    cudaGetSymbolAddress((void**)&k,     g_k);
    cudaGetSymbolAddress((void**)&v,     g_v);
    cudaGetSymbolAddress((void**)&v2,    g_v2);
    cudaGetSymbolAddress((void**)&hpre,  g_hpre);
    cudaGetSymbolAddress((void**)&kern,  g_kern);
    cudaGetSymbolAddress((void**)&o,     g_o);
    cudaGetSymbolAddress((void**)&xg,    g_xg);
    cudaGetSymbolAddress((void**)&beta,  g_beta);
    cudaGetSymbolAddress((void**)&decay, g_decay);
    cudaGetSymbolAddress((void**)&wth,   g_wth);
    cudaGetSymbolAddress((void**)&wtl,   g_wtl);
    cudaGetSymbolAddress((void**)&p0h,   g_p0h);
    cudaGetSymbolAddress((void**)&p0l,   g_p0l);
    cudaGetSymbolAddress((void**)&p1h,   g_p1h);
    cudaGetSymbolAddress((void**)&p1l,   g_p1l);

    const int SMEM = 81920;
    cudaFuncSetAttribute(gemm_cp, cudaFuncAttributeMaxDynamicSharedMemorySize, SMEM);

    // 0) weight prep: transpose + split
    {
        PrepBatch pb{};
        pb.W[0] = Wq;  pb.off[0] = OFF_Q;
        pb.W[1] = Wk;  pb.off[1] = OFF_K;
        pb.W[2] = Wv;  pb.off[2] = OFF_V;
        pb.W[3] = Wg;  pb.off[3] = OFF_G;
        pb.W[4] = W1;  pb.off[4] = OFF_W1A;
        pb.W[5] = W1 + 2048ll * 2048; pb.off[5] = OFF_W1B;
        pb.W[6] = Wo;  pb.off[6] = OFF_WO;
        prep_kernel<<<dim3(64, 64, 7), 256>>>(pb, wth, wtl, 2048);
        PrepBatch p2{};
        p2.W[0] = W2;  p2.off[0] = OFF_W2;
        prep_kernel<<<dim3(256, 64, 1), 256>>>(p2, wth, wtl, 8192);
    }
    // 0b) split x
    split_kernel<<<8192, 256>>>(x, p0h, p0l);
    // 1) fused projections: q,k,v,xg
    {
        GB bt{};
        for (int z = 0; z < 4; ++z) { bt.Ah[z] = p0h; bt.Al[z] = p0l; }
        bt.Bh[0] = wth + OFF_Q; bt.Bh[1] = wth + OFF_K; bt.Bh[2] = wth + OFF_V; bt.Bh[3] = wth + OFF_G;
        bt.Bl[0] = wtl + OFF_Q; bt.Bl[1] = wtl + OFF_K; bt.Bl[2] = wtl + OFF_V; bt.Bl[3] = wtl + OFF_G;
        bt.C[0] = q; bt.C[1] = k; bt.C[2] = v; bt.C[3] = xg;
        gemm_cp<<<dim3(16, 32, 4), 256, SMEM>>>(bt, 4096, 2048, 2048);
    }
    // gating params (only needs x)
    betag_kernel<<<256, 256>>>(x, Wb, Wa, dtb, Alog, beta, decay);
    // 2) split q,k; then generator layer 1 halves
    split_kernel<<<8192, 256>>>(q, p0h, p0l);
    split_kernel<<<8192, 256>>>(k, p1h, p1l);
    // l2norm can run now (raw q,k already captured in splits)
    l2norm_kernel<<<8192, 256>>>(q, k);
    {
        GB bt{};
        bt.Ah[0] = p0h; bt.Al[0] = p0l;
        bt.Ah[1] = p1h; bt.Al[1] = p1l;
        bt.Bh[0] = wth + OFF_W1A; bt.Bh[1] = wth + OFF_W1B;
        bt.Bl[0] = wtl + OFF_W1A; bt.Bl[1] = wtl + OFF_W1B;
        bt.C[0] = hpre; bt.C[1] = v2;
        gemm_cp<<<dim3(16, 32, 2), 256, SMEM>>>(bt, 4096, 2048, 2048);
    }
    // 3) h = silu(h0+h1) split, then generator layer 2
    silu_split_kernel<<<8192, 256>>>(hpre, v2, p0h, p0l);
    {
        GB bt{};
        bt.Ah[0] = p0h; bt.Al[0] = p0l;
        bt.Bh[0] = wth + OFF_W2;
        bt.Bl[0] = wtl + OFF_W2;
        bt.C[0] = kern;
        gemm_cp<<<dim3(64, 32, 1), 256, SMEM>>>(bt, 4096, 8192, 2048);
    }
    // 4) dynamic conv (+gen_b2) + SiLU
    conv_kernel<<<32768, 256>>>(kern, b2, v, v2);
    // 5) sequential recurrence
    recur_kernel<<<128, 256>>>(q, k, v2, decay, beta, o);
    // 6) gated RMSNorm -> og (hpre reused)
    rmsgate_kernel<<<8192, 256>>>(o, xg, nw, hpre);
    // 7) output projection
    split_kernel<<<8192, 256>>>(hpre, p0h, p0l);
    {
        GB bt{};
        bt.Ah[0] = p0h; bt.Al[0] = p0l;
        bt.Bh[0] = wth + OFF_WO;
        bt.Bl[0] = wtl + OFF_WO;
        bt.C[0] = out;
        gemm_cp<<<dim3(16, 32, 1), 256, SMEM>>>(bt, 4096, 2048, 2048);
    }
}

// round 6
// speedup vs baseline: 2.0840x; 1.2807x over previous
#include <cuda_runtime.h>
#include <cuda_bf16.h>
#include <mma.h>
#include <cstdint>

using namespace nvcuda;

// ---------------------------------------------------------------------------
// Dims (fixed): B=2, T=2048, HID=2048, H=16, DK=DV=128, W=4; rows = B*T = 4096
// Toolchain lowers to compute_103 PTX (no tcgen05). Stay sm_80-portable.
// ---------------------------------------------------------------------------

__device__ float g_q   [4096ll * 2048];
__device__ float g_k   [4096ll * 2048];
__device__ float g_v   [4096ll * 2048];
__device__ float g_v2  [4096ll * 2048];   // h1, then silu(conv(v))
__device__ float g_hpre[4096ll * 2048];   // h0, then og
__device__ float g_kern[4096ll * 8192];
__device__ float g_o   [4096ll * 2048];
__device__ float g_xg  [4096ll * 2048];
__device__ float g_beta [4096 * 16];
__device__ float g_decay[4096 * 16];

#define MELEM 4194304ll
#define OFF_Q   (0ll)
#define OFF_K   (1ll * MELEM)
#define OFF_V   (2ll * MELEM)
#define OFF_G   (3ll * MELEM)
#define OFF_W1A (4ll * MELEM)
#define OFF_W1B (5ll * MELEM)
#define OFF_WO  (6ll * MELEM)
#define OFF_W2  (7ll * MELEM)
__device__ __nv_bfloat16 g_wth[11ll * MELEM];
__device__ __nv_bfloat16 g_wtl[11ll * MELEM];

__device__ __nv_bfloat16 g_p0h[4096ll * 2048];
__device__ __nv_bfloat16 g_p0l[4096ll * 2048];
__device__ __nv_bfloat16 g_p1h[4096ll * 2048];
__device__ __nv_bfloat16 g_p1l[4096ll * 2048];

__device__ __forceinline__ float sigmoidf_(float x) { return 1.f / (1.f + expf(-x)); }

__device__ __forceinline__ uint32_t smem_u32(const void* p) {
    uint32_t a;
    asm("{ .reg .u64 t; cvta.to.shared.u64 t, %1; cvt.u32.u64 %0, t; }" : "=r"(a) : "l"(p));
    return a;
}
__device__ __forceinline__ void cp16(uint32_t so, const void* g) {
    asm volatile("cp.async.cg.shared.global [%0], [%1], 16;" :: "r"(so), "l"(g));
}
__device__ __forceinline__ void cp4(uint32_t so, const void* g) {
    asm volatile("cp.async.ca.shared.global [%0], [%1], 4;" :: "r"(so), "l"(g));
}

struct GB {
    const __nv_bfloat16* Ah[4];
    const __nv_bfloat16* Al[4];
    const __nv_bfloat16* Bh[4];
    const __nv_bfloat16* Bl[4];
    float*               C[4];
};

// ---------------------------------------------------------------------------
// Weight prep: transpose [K,N] fp32 -> [N,K] bf16 hi/lo split
// ---------------------------------------------------------------------------
struct PrepBatch { const float* W[7]; long long off[7]; };

__global__ void __launch_bounds__(256) prep_kernel(
    PrepBatch pb, __nv_bfloat16* __restrict__ Th, __nv_bfloat16* __restrict__ Tl, int N)
{
    __shared__ float s[32][33];
    const float* W = pb.W[blockIdx.z];
    const long long base = pb.off[blockIdx.z];
    const int n0 = blockIdx.x * 32, k0 = blockIdx.y * 32;
    const int tid = threadIdx.x;
#pragma unroll
    for (int j = 0; j < 4; ++j) {
        int lin = tid + j * 256;
        int kk = lin >> 5, nn = lin & 31;
        s[kk][nn] = W[(size_t)(k0 + kk) * N + n0 + nn];
    }
    __syncthreads();
#pragma unroll
    for (int j = 0; j < 4; ++j) {
        int lin = tid + j * 256;
        int nn = lin >> 5, kk = lin & 31;
        float v = s[kk][nn];
        __nv_bfloat16 h = __float2bfloat16_rn(v);
        __nv_bfloat16 l = __float2bfloat16_rn(v - __bfloat162float(h));
        size_t o = (size_t)base + (size_t)(n0 + nn) * 2048 + k0 + kk;
        Th[o] = h;
        Tl[o] = l;
    }
}

// ---------------------------------------------------------------------------
// Elementwise fp32 -> bf16 hi/lo split
// ---------------------------------------------------------------------------
__device__ __forceinline__ void split4_store(
    float4 v, __nv_bfloat16* __restrict__ h, __nv_bfloat16* __restrict__ l, size_t i)
{
    __nv_bfloat16 hx = __float2bfloat16_rn(v.x), hy = __float2bfloat16_rn(v.y);
    __nv_bfloat16 hz = __float2bfloat16_rn(v.z), hw = __float2bfloat16_rn(v.w);
    __nv_bfloat16 lx = __float2bfloat16_rn(v.x - __bfloat162float(hx));
    __nv_bfloat16 ly = __float2bfloat16_rn(v.y - __bfloat162float(hy));
    __nv_bfloat16 lz = __float2bfloat16_rn(v.z - __bfloat162float(hz));
    __nv_bfloat16 lw = __float2bfloat16_rn(v.w - __bfloat162float(hw));
    __nv_bfloat162 h0(hx, hy), h1(hz, hw), l0(lx, ly), l1(lz, lw);
    *(uint2*)(h + i) = make_uint2(*(uint32_t*)&h0, *(uint32_t*)&h1);
    *(uint2*)(l + i) = make_uint2(*(uint32_t*)&l0, *(uint32_t*)&l1);
}

__global__ void __launch_bounds__(256) split_kernel(
    const float* __restrict__ s, __nv_bfloat16* __restrict__ h, __nv_bfloat16* __restrict__ l)
{
    size_t i = ((size_t)blockIdx.x * 256 + threadIdx.x) * 4;
    split4_store(*(const float4*)(s + i), h, l, i);
}

__global__ void __launch_bounds__(256) silu_split_kernel(
    const float* __restrict__ a, const float* __restrict__ b,
    __nv_bfloat16* __restrict__ h, __nv_bfloat16* __restrict__ l)
{
    size_t i = ((size_t)blockIdx.x * 256 + threadIdx.x) * 4;
    float4 va = *(const float4*)(a + i);
    float4 vb = *(const float4*)(b + i);
    float4 v;
    float sx = va.x + vb.x, sy = va.y + vb.y, sz = va.z + vb.z, sw = va.w + vb.w;
    v.x = sx * sigmoidf_(sx);
    v.y = sy * sigmoidf_(sy);
    v.z = sz * sigmoidf_(sz);
    v.w = sw * sigmoidf_(sw);
    split4_store(v, h, l, i);
}

// ---------------------------------------------------------------------------
// Split-bf16 HMMA GEMM with cp.async pipeline (unchanged from R5 pass).
// ---------------------------------------------------------------------------
__global__ void __launch_bounds__(256, 2) gemm_cp(
    GB bt, int M, int N, int K)
{
    extern __shared__ __align__(16) char dsm[];
    const int tid = threadIdx.x;
    const int wid = tid >> 5;
    const int wm  = wid >> 2;
    const int wn  = wid & 3;
    const int m0  = blockIdx.y << 7;
    const int n0  = blockIdx.x << 7;
    const __nv_bfloat16* __restrict__ Ah = bt.Ah[blockIdx.z];
    const __nv_bfloat16* __restrict__ Al = bt.Al[blockIdx.z];
    const __nv_bfloat16* __restrict__ Bh = bt.Bh[blockIdx.z];
    const __nv_bfloat16* __restrict__ Bl = bt.Bl[blockIdx.z];
    float* __restrict__ C = bt.C[blockIdx.z];

    const uint32_t sbase = smem_u32(dsm);
    const int r0 = tid >> 2, c16 = tid & 3;
    const int r1 = r0 + 64;

    auto issue = [&](int s, int kc) {
        const uint32_t sb = sbase + s * 40960;
        const size_t ka = (size_t)kc * 32 + c16 * 8;
        {
            uint32_t so = sb + r0 * 80 + c16 * 16;
            cp16(so,         Ah + (size_t)(m0 + r0) * K + ka);
            cp16(so + 10240, Al + (size_t)(m0 + r0) * K + ka);
            cp16(so + 20480, Bh + (size_t)(n0 + r0) * K + ka);
            cp16(so + 30720, Bl + (size_t)(n0 + r0) * K + ka);
        }
        {
            uint32_t so = sb + r1 * 80 + c16 * 16;
            cp16(so,         Ah + (size_t)(m0 + r1) * K + ka);
            cp16(so + 10240, Al + (size_t)(m0 + r1) * K + ka);
            cp16(so + 20480, Bh + (size_t)(n0 + r1) * K + ka);
            cp16(so + 30720, Bl + (size_t)(n0 + r1) * K + ka);
        }
    };

    wmma::fragment<wmma::accumulator, 16, 16, 16, float> acc[4][2];
#pragma unroll
    for (int i = 0; i < 4; ++i)
#pragma unroll
        for (int j = 0; j < 2; ++j) wmma::fill_fragment(acc[i][j], 0.f);

    issue(0, 0);
    asm volatile("cp.async.commit_group;");

    const int NC = K >> 5;
    for (int c = 0; c < NC; ++c) {
        const int s = c & 1;
        if (c + 1 < NC) issue(s ^ 1, c + 1);
        asm volatile("cp.async.commit_group;");
        asm volatile("cp.async.wait_group 1;");
        __syncthreads();

        const __nv_bfloat16* ah = (const __nv_bfloat16*)(dsm + s * 40960);
        const __nv_bfloat16* al = (const __nv_bfloat16*)(dsm + s * 40960 + 10240);
        const __nv_bfloat16* bh = (const __nv_bfloat16*)(dsm + s * 40960 + 20480);
        const __nv_bfloat16* bl = (const __nv_bfloat16*)(dsm + s * 40960 + 30720);

#pragma unroll
        for (int kk = 0; kk < 2; ++kk) {
            wmma::fragment<wmma::matrix_b, 16, 16, 16, __nv_bfloat16, wmma::col_major> bfh[2], bfl[2];
#pragma unroll
            for (int ni = 0; ni < 2; ++ni) {
                wmma::load_matrix_sync(bfh[ni], bh + (wn * 32 + ni * 16) * 40 + kk * 16, 40);
                wmma::load_matrix_sync(bfl[ni], bl + (wn * 32 + ni * 16) * 40 + kk * 16, 40);
            }
#pragma unroll
            for (int mi = 0; mi < 4; ++mi) {
                wmma::fragment<wmma::matrix_a, 16, 16, 16, __nv_bfloat16, wmma::row_major> afh, afl;
                wmma::load_matrix_sync(afh, ah + (wm * 64 + mi * 16) * 40 + kk * 16, 40);
                wmma::load_matrix_sync(afl, al + (wm * 64 + mi * 16) * 40 + kk * 16, 40);
#pragma unroll
                for (int ni = 0; ni < 2; ++ni) {
                    wmma::mma_sync(acc[mi][ni], afh, bfl[ni], acc[mi][ni]);
                    wmma::mma_sync(acc[mi][ni], afl, bfh[ni], acc[mi][ni]);
                    wmma::mma_sync(acc[mi][ni], afh, bfh[ni], acc[mi][ni]);
                }
            }
        }
        __syncthreads();
    }

#pragma unroll
    for (int mi = 0; mi < 4; ++mi)
#pragma unroll
        for (int ni = 0; ni < 2; ++ni)
            wmma::store_matrix_sync(C + (size_t)(m0 + wm * 64 + mi * 16) * N + n0 + wn * 32 + ni * 16,
                                    acc[mi][ni], N, wmma::mem_row_major);
}

// ---------------------------------------------------------------------------
// Dynamic short conv (W=4, causal) + bias + SiLU.
// ---------------------------------------------------------------------------
__global__ void __launch_bounds__(256) conv_kernel(
    const float* __restrict__ kern, const float* __restrict__ b2,
    const float* __restrict__ v, float* __restrict__ v2)
{
    int idx = blockIdx.x * 256 + threadIdx.x;
    int row = idx >> 11;
    int d   = idx & 2047;
    int t   = row & 2047;
    float4 kf = *(const float4*)(kern + (size_t)row * 8192 + d * 4);
    float4 bv = *(const float4*)(b2 + d * 4);
    kf.x += bv.x; kf.y += bv.y; kf.z += bv.z; kf.w += bv.w;
    size_t base = (size_t)row * 2048 + d;
    float acc = kf.w * v[base];
    if (t >= 1) acc += kf.z * v[base - 2048];
    if (t >= 2) acc += kf.y * v[base - 4096];
    if (t >= 3) acc += kf.x * v[base - 6144];
    v2[base] = acc * sigmoidf_(acc);
}

// ---------------------------------------------------------------------------
// beta / decay
// ---------------------------------------------------------------------------
__global__ void __launch_bounds__(256) betag_kernel(
    const float* __restrict__ x, const float* __restrict__ Wb, const float* __restrict__ Wa,
    const float* __restrict__ dtb, const float* __restrict__ Alog,
    float* __restrict__ beta, float* __restrict__ decay)
{
    __shared__ float xs[16][128];
    __shared__ float wbs[128 * 17];
    __shared__ float was[128 * 17];
    const int tid = threadIdx.x;
    const int myrow = tid >> 4, mycol = tid & 15;
    const int r0 = blockIdx.x * 16;
    float pb = 0.f, pa = 0.f;
    for (int ch = 0; ch < 16; ++ch) {
        __syncthreads();
#pragma unroll
        for (int j = 0; j < 8; ++j) {
            int lin = tid + j * 256;
            int rr = lin >> 7, cc = lin & 127;
            xs[rr][cc] = x[(size_t)(r0 + rr) * 2048 + ch * 128 + cc];
            int wi = lin >> 4, wc = lin & 15;
            wbs[wi * 17 + wc] = Wb[(size_t)ch * 2048 + lin];
            was[wi * 17 + wc] = Wa[(size_t)ch * 2048 + lin];
        }
        __syncthreads();
#pragma unroll 8
        for (int i = 0; i < 128; ++i) {
            float xv = xs[myrow][i];
            pb = fmaf(xv, wbs[i * 17 + mycol], pb);
            pa = fmaf(xv, was[i * 17 + mycol], pa);
        }
    }
    int row = r0 + myrow;
    beta[row * 16 + mycol] = 1.f / (1.f + expf(-pb));
    float z = pa + dtb[mycol];
    float sp = (z > 20.f) ? z : log1pf(expf(z));
    decay[row * 16 + mycol] = expf(-expf(Alog[mycol]) * sp);
}

// ---------------------------------------------------------------------------
// In-place L2 normalize q and k per (row, head) of 128
// ---------------------------------------------------------------------------
__global__ void __launch_bounds__(256) l2norm_kernel(float* __restrict__ q, float* __restrict__ k)
{
    int u = blockIdx.x * 8 + (threadIdx.x >> 5);
    int lane = threadIdx.x & 31;
    size_t base = (size_t)u * 128 + lane * 4;
    {
        float4 a = *(float4*)(q + base);
        float ss = a.x * a.x + a.y * a.y + a.z * a.z + a.w * a.w;
#pragma unroll
        for (int m = 16; m >= 1; m >>= 1) ss += __shfl_xor_sync(0xffffffffu, ss, m);
        float sc = 1.f / fmaxf(sqrtf(ss), 1e-12f);
        a.x *= sc; a.y *= sc; a.z *= sc; a.w *= sc;
        *(float4*)(q + base) = a;
    }
    {
        float4 a = *(float4*)(k + base);
        float ss = a.x * a.x + a.y * a.y + a.z * a.z + a.w * a.w;
#pragma unroll
        for (int m = 16; m >= 1; m >>= 1) ss += __shfl_xor_sync(0xffffffffu, ss, m);
        float sc = 1.f / fmaxf(sqrtf(ss), 1e-12f);
        a.x *= sc; a.y *= sc; a.z *= sc; a.w *= sc;
        *(float4*)(k + base) = a;
    }
}

// ---------------------------------------------------------------------------
// Gated delta rule recurrence, time-tiled with cp.async.
// 128 CTAs = (b,h,dvblk32); 256 threads: dkg = tid&7, dvi = tid>>3.
// Thread's dk slice = float4 chunks {dkg + 8j}, j=0..3 (conflict-free LDS,
// permutation-invariant for all dot products / updates).
// TT=16 steps per tile, double-buffered; 2 barriers per tile (not per step).
// ---------------------------------------------------------------------------
#define TT 16
__global__ void __launch_bounds__(256, 1) recur_kernel(
    const float* __restrict__ qn, const float* __restrict__ kn,
    const float* __restrict__ v, const float* __restrict__ decay,
    const float* __restrict__ beta, float* __restrict__ o)
{
    __shared__ float qt[2][TT * 128];
    __shared__ float kt[2][TT * 128];
    __shared__ float vt[2][TT * 32];
    __shared__ float gt[2][TT];
    __shared__ float bt[2][TT];
    __shared__ float ob[TT * 32];

    const int bx = blockIdx.x;
    const int bh = bx >> 2;
    const int dvblk = bx & 3;
    const int b = bh >> 4;
    const int h = bh & 15;
    const int tid = threadIdx.x;
    const int dkg = tid & 7;
    const int dvi = tid >> 3;

    const size_t row0 = (size_t)b * 2048;
    const float* qrow = qn + row0 * 2048 + h * 128;
    const float* krow = kn + row0 * 2048 + h * 128;
    const float* vrow = v + row0 * 2048 + h * 128 + dvblk * 32;
    const float* grow = decay + row0 * 16 + h;
    const float* brow = beta + row0 * 16 + h;
    float* obase = o + row0 * 2048 + h * 128 + dvblk * 32;

    float S[16];
#pragma unroll
    for (int i = 0; i < 16; ++i) S[i] = 0.f;

    auto issue_tile = [&](int tt, int buf) {
        const int t0 = tt * TT;
        // q, k: 512 16B-chunks each; this thread does chunks tid and tid+256
#pragma unroll
        for (int j = 0; j < 2; ++j) {
            int c = tid + j * 256;
            int st = c >> 5, of = c & 31;
            const float* gq = qrow + (size_t)(t0 + st) * 2048 + of * 4;
            const float* gk = krow + (size_t)(t0 + st) * 2048 + of * 4;
            cp16(smem_u32(&qt[buf][st * 128 + of * 4]), gq);
            cp16(smem_u32(&kt[buf][st * 128 + of * 4]), gk);
        }
        if (tid < 128) {
            int st = tid >> 3, of = tid & 7;
            cp16(smem_u32(&vt[buf][st * 32 + of * 4]),
                 vrow + (size_t)(t0 + st) * 2048 + of * 4);
        } else if (tid < 144) {
            int i = tid - 128;
            cp4(smem_u32(&gt[buf][i]), grow + (size_t)(t0 + i) * 16);
        } else if (tid < 160) {
            int i = tid - 144;
            cp4(smem_u32(&bt[buf][i]), brow + (size_t)(t0 + i) * 16);
        }
    };

    issue_tile(0, 0);
    asm volatile("cp.async.commit_group;");

    const int NT = 2048 / TT;   // 128
    for (int tt = 0; tt < NT; ++tt) {
        asm volatile("cp.async.wait_group 0;");
        __syncthreads();
        const int buf = tt & 1;
        if (tt + 1 < NT) issue_tile(tt + 1, buf ^ 1);
        asm volatile("cp.async.commit_group;");

#pragma unroll 4
        for (int st = 0; st < TT; ++st) {
            float qv[16], kv[16];
#pragma unroll
            for (int j = 0; j < 4; ++j) {
                float4 a = *(const float4*)&qt[buf][st * 128 + (dkg + 8 * j) * 4];
                qv[j * 4 + 0] = a.x; qv[j * 4 + 1] = a.y; qv[j * 4 + 2] = a.z; qv[j * 4 + 3] = a.w;
                float4 c = *(const float4*)&kt[buf][st * 128 + (dkg + 8 * j) * 4];
                kv[j * 4 + 0] = c.x; kv[j * 4 + 1] = c.y; kv[j * 4 + 2] = c.z; kv[j * 4 + 3] = c.w;
            }
            float o0 = 0.f, o1 = 0.f, s0 = 0.f, s1 = 0.f;
#pragma unroll
            for (int i = 0; i < 16; i += 2) {
                o0 = fmaf(S[i],     qv[i],     o0);
                o1 = fmaf(S[i + 1], qv[i + 1], o1);
                s0 = fmaf(S[i],     kv[i],     s0);
                s1 = fmaf(S[i + 1], kv[i + 1], s1);
            }
            float ot = o0 + o1, sk = s0 + s1;
#pragma unroll
            for (int m = 4; m >= 1; m >>= 1) {
                ot += __shfl_xor_sync(0xffffffffu, ot, m);
                sk += __shfl_xor_sync(0xffffffffu, sk, m);
            }
            const float gv = gt[buf][st];
            const float bv = bt[buf][st];
            const float vv = vt[buf][st * 32 + dvi];
            const float cc = bv * (vv - sk);
#pragma unroll
            for (int i = 0; i < 16; ++i)
                S[i] = fmaf(cc, kv[i], S[i] * gv);
            if (dkg == 0) ob[st * 32 + dvi] = ot;
        }
        __syncthreads();
        // coalesced o write for this tile
        if (tid < 128) {
            int st = tid >> 3, of = tid & 7;
            float4 val = *(const float4*)&ob[st * 32 + of * 4];
            *(float4*)(obase + (size_t)(tt * TT + st) * 2048 + of * 4) = val;
        }
    }
}

// ---------------------------------------------------------------------------
// Gated RMSNorm
// ---------------------------------------------------------------------------
__global__ void __launch_bounds__(256) rmsgate_kernel(
    const float* __restrict__ o, const float* __restrict__ xg,
    const float* __restrict__ nw, float* __restrict__ og)
{
    int u = blockIdx.x * 8 + (threadIdx.x >> 5);
    int lane = threadIdx.x & 31;
    size_t base = (size_t)u * 128 + lane * 4;
    float4 a = *(const float4*)(o + base);
    float ss = a.x * a.x + a.y * a.y + a.z * a.z + a.w * a.w;
#pragma unroll
    for (int m = 16; m >= 1; m >>= 1) ss += __shfl_xor_sync(0xffffffffu, ss, m);
    float r = rsqrtf(ss * (1.f / 128.f) + 1e-6f);
    float4 g = *(const float4*)(xg + base);
    float4 w = *(const float4*)(nw + lane * 4);
    float4 out;
    out.x = a.x * r * w.x * (g.x * sigmoidf_(g.x));
    out.y = a.y * r * w.y * (g.y * sigmoidf_(g.y));
    out.z = a.z * r * w.z * (g.z * sigmoidf_(g.z));
    out.w = a.w * r * w.w * (g.w * sigmoidf_(g.w));
    *(float4*)(og + base) = out;
}

// ---------------------------------------------------------------------------
extern "C" void kernel_launch(void* const* d_in, const int* in_sizes, int n_in,
                              void* d_out, int out_size)
{
    const float* x    = (const float*)d_in[0];
    const float* Wq   = (const float*)d_in[1];
    const float* Wk   = (const float*)d_in[2];
    const float* Wv   = (const float*)d_in[3];
    const float* Wb   = (const float*)d_in[4];
    const float* Wa   = (const float*)d_in[5];
    const float* dtb  = (const float*)d_in[6];
    const float* Alog = (const float*)d_in[7];
    const float* W1   = (const float*)d_in[8];
    const float* W2   = (const float*)d_in[9];
    const float* b2   = (const float*)d_in[10];
    const float* nw   = (const float*)d_in[11];
    const float* Wg   = (const float*)d_in[12];
    const float* Wo   = (const float*)d_in[13];
    float* out = (float*)d_out;

    float *q, *k, *v, *v2, *hpre, *kern, *o, *xg, *beta, *decay;
    __nv_bfloat16 *wth, *wtl, *p0h, *p0l, *p1h, *p1l;
    cudaGetSymbolAddress((void**)&q,     g_q);
    cudaGetSymbolAddress((void**)&k,     g_k);
    cudaGetSymbolAddress((void**)&v,     g_v);
    cudaGetSymbolAddress((void**)&v2,    g_v2);
    cudaGetSymbolAddress((void**)&hpre,  g_hpre);
    cudaGetSymbolAddress((void**)&kern,  g_kern);
    cudaGetSymbolAddress((void**)&o,     g_o);
    cudaGetSymbolAddress((void**)&xg,    g_xg);
    cudaGetSymbolAddress((void**)&beta,  g_beta);
    cudaGetSymbolAddress((void**)&decay, g_decay);
    cudaGetSymbolAddress((void**)&wth,   g_wth);
    cudaGetSymbolAddress((void**)&wtl,   g_wtl);
    cudaGetSymbolAddress((void**)&p0h,   g_p0h);
    cudaGetSymbolAddress((void**)&p0l,   g_p0l);
    cudaGetSymbolAddress((void**)&p1h,   g_p1h);
    cudaGetSymbolAddress((void**)&p1l,   g_p1l);

    const int SMEM = 81920;
    cudaFuncSetAttribute(gemm_cp, cudaFuncAttributeMaxDynamicSharedMemorySize, SMEM);

    // 0) weight prep
    {
        PrepBatch pb{};
        pb.W[0] = Wq;  pb.off[0] = OFF_Q;
        pb.W[1] = Wk;  pb.off[1] = OFF_K;
        pb.W[2] = Wv;  pb.off[2] = OFF_V;
        pb.W[3] = Wg;  pb.off[3] = OFF_G;
        pb.W[4] = W1;  pb.off[4] = OFF_W1A;
        pb.W[5] = W1 + 2048ll * 2048; pb.off[5] = OFF_W1B;
        pb.W[6] = Wo;  pb.off[6] = OFF_WO;
        prep_kernel<<<dim3(64, 64, 7), 256>>>(pb, wth, wtl, 2048);
        PrepBatch p2{};
        p2.W[0] = W2;  p2.off[0] = OFF_W2;
        prep_kernel<<<dim3(256, 64, 1), 256>>>(p2, wth, wtl, 8192);
    }
    // 0b) split x
    split_kernel<<<8192, 256>>>(x, p0h, p0l);
    // 1) fused projections
    {
        GB bt{};
        for (int z = 0; z < 4; ++z) { bt.Ah[z] = p0h; bt.Al[z] = p0l; }
        bt.Bh[0] = wth + OFF_Q; bt.Bh[1] = wth + OFF_K; bt.Bh[2] = wth + OFF_V; bt.Bh[3] = wth + OFF_G;
        bt.Bl[0] = wtl + OFF_Q; bt.Bl[1] = wtl + OFF_K; bt.Bl[2] = wtl + OFF_V; bt.Bl[3] = wtl + OFF_G;
        bt.C[0] = q; bt.C[1] = k; bt.C[2] = v; bt.C[3] = xg;
        gemm_cp<<<dim3(16, 32, 4), 256, SMEM>>>(bt, 4096, 2048, 2048);
    }
    betag_kernel<<<256, 256>>>(x, Wb, Wa, dtb, Alog, beta, decay);
    // 2) split q,k; gen layer 1
    split_kernel<<<8192, 256>>>(q, p0h, p0l);
    split_kernel<<<8192, 256>>>(k, p1h, p1l);
    l2norm_kernel<<<8192, 256>>>(q, k);
    {
        GB bt{};
        bt.Ah[0] = p0h; bt.Al[0] = p0l;
        bt.Ah[1] = p1h; bt.Al[1] = p1l;
        bt.Bh[0] = wth + OFF_W1A; bt.Bh[1] = wth + OFF_W1B;
        bt.Bl[0] = wtl + OFF_W1A; bt.Bl[1] = wtl + OFF_W1B;
        bt.C[0] = hpre; bt.C[1] = v2;
        gemm_cp<<<dim3(16, 32, 2), 256, SMEM>>>(bt, 4096, 2048, 2048);
    }
    // 3) silu(h0+h1) split; gen layer 2
    silu_split_kernel<<<8192, 256>>>(hpre, v2, p0h, p0l);
    {
        GB bt{};
        bt.Ah[0] = p0h; bt.Al[0] = p0l;
        bt.Bh[0] = wth + OFF_W2;
        bt.Bl[0] = wtl + OFF_W2;
        bt.C[0] = kern;
        gemm_cp<<<dim3(64, 32, 1), 256, SMEM>>>(bt, 4096, 8192, 2048);
    }
    // 4) conv (+bias) + SiLU
    conv_kernel<<<32768, 256>>>(kern, b2, v, v2);
    // 5) recurrence (time-tiled)
    recur_kernel<<<128, 256>>>(q, k, v2, decay, beta, o);
    // 6) gated RMSNorm
    rmsgate_kernel<<<8192, 256>>>(o, xg, nw, hpre);
    // 7) output projection
    split_kernel<<<8192, 256>>>(hpre, p0h, p0l);
    {
        GB bt{};
        bt.Ah[0] = p0h; bt.Al[0] = p0l;
        bt.Bh[0] = wth + OFF_WO;
        bt.Bl[0] = wtl + OFF_WO;
        bt.C[0] = out;
        gemm_cp<<<dim3(16, 32, 1), 256, SMEM>>>(bt, 4096, 2048, 2048);
    }
}

// round 7
// speedup vs baseline: 2.1073x; 1.0112x over previous
#include <cuda_runtime.h>
#include <cuda_bf16.h>
#include <mma.h>
#include <cstdint>

using namespace nvcuda;

// ---------------------------------------------------------------------------
// Dims (fixed): B=2, T=2048, HID=2048, H=16, DK=DV=128, W=4; rows = B*T = 4096
// Toolchain lowers to compute_103 PTX (no tcgen05). Stay sm_80-portable.
// ---------------------------------------------------------------------------

__device__ float g_q   [4096ll * 2048];   // NORMALIZED q (proj epilogue)
__device__ float g_k   [4096ll * 2048];   // NORMALIZED k
__device__ float g_v   [4096ll * 2048];   // raw v
__device__ float g_v2  [4096ll * 2048];   // silu(conv(v))  (gen2 epilogue)
__device__ float g_o   [4096ll * 2048];   // recurrence output
__device__ float g_xg  [4096ll * 2048];   // gate projection
__device__ float g_beta [4096 * 16];
__device__ float g_decay[4096 * 16];

#define MELEM 4194304ll
#define OFF_Q   (0ll)
#define OFF_K   (1ll * MELEM)
#define OFF_V   (2ll * MELEM)
#define OFF_G   (3ll * MELEM)
#define OFF_W1  (4ll * MELEM)           // [2048, 4096] spans 2 slots
#define OFF_WO  (6ll * MELEM)
#define OFF_W2  (7ll * MELEM)           // [8192, 2048] spans 4 slots
__device__ __nv_bfloat16 g_wth[11ll * MELEM];
__device__ __nv_bfloat16 g_wtl[11ll * MELEM];

// split activation buffers
__device__ __nv_bfloat16 g_p0h[4096ll * 2048];  // x split -> gen1 out split -> og split
__device__ __nv_bfloat16 g_p0l[4096ll * 2048];
__device__ __nv_bfloat16 g_pqh[4096ll * 4096];  // raw concat(q,k) split
__device__ __nv_bfloat16 g_pql[4096ll * 4096];

__device__ __forceinline__ float sigmoidf_(float x) { return 1.f / (1.f + expf(-x)); }

__device__ __forceinline__ uint32_t smem_u32(const void* p) {
    uint32_t a;
    asm("{ .reg .u64 t; cvta.to.shared.u64 t, %1; cvt.u32.u64 %0, t; }" : "=r"(a) : "l"(p));
    return a;
}
__device__ __forceinline__ void cp16(uint32_t so, const void* g) {
    asm volatile("cp.async.cg.shared.global [%0], [%1], 16;" :: "r"(so), "l"(g));
}
__device__ __forceinline__ void cp4(uint32_t so, const void* g) {
    asm volatile("cp.async.ca.shared.global [%0], [%1], 4;" :: "r"(so), "l"(g));
}

__device__ __forceinline__ void split2(float x, float y, uint32_t& hu, uint32_t& lu) {
    __nv_bfloat16 hx = __float2bfloat16_rn(x), hy = __float2bfloat16_rn(y);
    __nv_bfloat16 lx = __float2bfloat16_rn(x - __bfloat162float(hx));
    __nv_bfloat16 ly = __float2bfloat16_rn(y - __bfloat162float(hy));
    __nv_bfloat162 h(hx, hy), l(lx, ly);
    hu = *(uint32_t*)&h;
    lu = *(uint32_t*)&l;
}
__device__ __forceinline__ void split4_store(
    float4 v, __nv_bfloat16* __restrict__ h, __nv_bfloat16* __restrict__ l, size_t i)
{
    uint2 hu, lu;
    split2(v.x, v.y, hu.x, lu.x);
    split2(v.z, v.w, hu.y, lu.y);
    *(uint2*)(h + i) = hu;
    *(uint2*)(l + i) = lu;
}

// ---------------------------------------------------------------------------
// Weight prep: transpose [K,N] fp32 -> [N,K] bf16 hi/lo split (stride Kd)
// ---------------------------------------------------------------------------
struct PrepBatch { const float* W[5]; long long off[5]; };

__global__ void __launch_bounds__(256) prep_kernel(
    PrepBatch pb, __nv_bfloat16* __restrict__ Th, __nv_bfloat16* __restrict__ Tl,
    int N, int Kd)
{
    __shared__ float s[32][33];
    const float* W = pb.W[blockIdx.z];
    const long long base = pb.off[blockIdx.z];
    const int n0 = blockIdx.x * 32, k0 = blockIdx.y * 32;
    const int tid = threadIdx.x;
#pragma unroll
    for (int j = 0; j < 4; ++j) {
        int lin = tid + j * 256;
        int kk = lin >> 5, nn = lin & 31;
        s[kk][nn] = W[(size_t)(k0 + kk) * N + n0 + nn];
    }
    __syncthreads();
#pragma unroll
    for (int j = 0; j < 4; ++j) {
        int lin = tid + j * 256;
        int nn = lin >> 5, kk = lin & 31;
        float v = s[kk][nn];
        __nv_bfloat16 h = __float2bfloat16_rn(v);
        __nv_bfloat16 l = __float2bfloat16_rn(v - __bfloat162float(h));
        size_t o = (size_t)base + (size_t)(n0 + nn) * Kd + k0 + kk;
        Th[o] = h;
        Tl[o] = l;
    }
}

__global__ void __launch_bounds__(256) split_kernel(
    const float* __restrict__ s, __nv_bfloat16* __restrict__ h, __nv_bfloat16* __restrict__ l)
{
    size_t i = ((size_t)blockIdx.x * 256 + threadIdx.x) * 4;
    split4_store(*(const float4*)(s + i), h, l, i);
}

// ---------------------------------------------------------------------------
// Split-bf16 HMMA GEMM, cp.async pipeline, fused epilogues.
// EPI 0: plain fp32 store.
// EPI 1: q/k proj: per-row (head) L2 norm -> normalized fp32 to C; raw split
//        bf16 into eh/el at row*estride + ecol + n.
// EPI 2: silu(acc) -> split bf16 into eh/el (no fp32).
// EPI 3: dynamic conv: acc tile = kern[row, d, w] (pre-bias); add bias, conv
//        against vsrc, SiLU, write fp32 to C (v2 layout [row, 2048]).
// ---------------------------------------------------------------------------
struct GB {
    const __nv_bfloat16* Ah[4]; const __nv_bfloat16* Al[4];
    const __nv_bfloat16* Bh[4]; const __nv_bfloat16* Bl[4];
    float* C[4];
    int epi[4];
    __nv_bfloat16* eh[4]; __nv_bfloat16* el[4];
    long long estride[4]; long long ecol[4];
    const float* vsrc; const float* bias;
};

#define EPS 140   // epilogue smem row stride (words); 35 mod 32 coprime -> row reads conflict-free

__global__ void __launch_bounds__(256, 2) gemm_cp(
    GB bt, int M, int N, int K)
{
    extern __shared__ __align__(16) char dsm[];
    __shared__ float sc[128];
    const int tid = threadIdx.x;
    const int wid = tid >> 5;
    const int wm  = wid >> 2;
    const int wn  = wid & 3;
    const int m0  = blockIdx.y << 7;
    const int n0  = blockIdx.x << 7;
    const int z   = blockIdx.z;
    const __nv_bfloat16* __restrict__ Ah = bt.Ah[z];
    const __nv_bfloat16* __restrict__ Al = bt.Al[z];
    const __nv_bfloat16* __restrict__ Bh = bt.Bh[z];
    const __nv_bfloat16* __restrict__ Bl = bt.Bl[z];
    float* __restrict__ C = bt.C[z];

    const uint32_t sbase = smem_u32(dsm);
    const int r0 = tid >> 2, c16 = tid & 3;
    const int r1 = r0 + 64;

    auto issue = [&](int s, int kc) {
        const uint32_t sb = sbase + s * 40960;
        const size_t ka = (size_t)kc * 32 + c16 * 8;
        {
            uint32_t so = sb + r0 * 80 + c16 * 16;
            cp16(so,         Ah + (size_t)(m0 + r0) * K + ka);
            cp16(so + 10240, Al + (size_t)(m0 + r0) * K + ka);
            cp16(so + 20480, Bh + (size_t)(n0 + r0) * K + ka);
            cp16(so + 30720, Bl + (size_t)(n0 + r0) * K + ka);
        }
        {
            uint32_t so = sb + r1 * 80 + c16 * 16;
            cp16(so,         Ah + (size_t)(m0 + r1) * K + ka);
            cp16(so + 10240, Al + (size_t)(m0 + r1) * K + ka);
            cp16(so + 20480, Bh + (size_t)(n0 + r1) * K + ka);
            cp16(so + 30720, Bl + (size_t)(n0 + r1) * K + ka);
        }
    };

    wmma::fragment<wmma::accumulator, 16, 16, 16, float> acc[4][2];
#pragma unroll
    for (int i = 0; i < 4; ++i)
#pragma unroll
        for (int j = 0; j < 2; ++j) wmma::fill_fragment(acc[i][j], 0.f);

    issue(0, 0);
    asm volatile("cp.async.commit_group;");

    const int NC = K >> 5;
    for (int c = 0; c < NC; ++c) {
        const int s = c & 1;
        if (c + 1 < NC) issue(s ^ 1, c + 1);
        asm volatile("cp.async.commit_group;");
        asm volatile("cp.async.wait_group 1;");
        __syncthreads();

        const __nv_bfloat16* ah = (const __nv_bfloat16*)(dsm + s * 40960);
        const __nv_bfloat16* al = (const __nv_bfloat16*)(dsm + s * 40960 + 10240);
        const __nv_bfloat16* bh = (const __nv_bfloat16*)(dsm + s * 40960 + 20480);
        const __nv_bfloat16* bl = (const __nv_bfloat16*)(dsm + s * 40960 + 30720);

#pragma unroll
        for (int kk = 0; kk < 2; ++kk) {
            wmma::fragment<wmma::matrix_b, 16, 16, 16, __nv_bfloat16, wmma::col_major> bfh[2], bfl[2];
#pragma unroll
            for (int ni = 0; ni < 2; ++ni) {
                wmma::load_matrix_sync(bfh[ni], bh + (wn * 32 + ni * 16) * 40 + kk * 16, 40);
                wmma::load_matrix_sync(bfl[ni], bl + (wn * 32 + ni * 16) * 40 + kk * 16, 40);
            }
#pragma unroll
            for (int mi = 0; mi < 4; ++mi) {
                wmma::fragment<wmma::matrix_a, 16, 16, 16, __nv_bfloat16, wmma::row_major> afh, afl;
                wmma::load_matrix_sync(afh, ah + (wm * 64 + mi * 16) * 40 + kk * 16, 40);
                wmma::load_matrix_sync(afl, al + (wm * 64 + mi * 16) * 40 + kk * 16, 40);
#pragma unroll
                for (int ni = 0; ni < 2; ++ni) {
                    wmma::mma_sync(acc[mi][ni], afh, bfl[ni], acc[mi][ni]);
                    wmma::mma_sync(acc[mi][ni], afl, bfh[ni], acc[mi][ni]);
                    wmma::mma_sync(acc[mi][ni], afh, bfh[ni], acc[mi][ni]);
                }
            }
        }
        __syncthreads();
    }

    const int epi_mode = bt.epi[z];
    if (epi_mode == 0) {
#pragma unroll
        for (int mi = 0; mi < 4; ++mi)
#pragma unroll
            for (int ni = 0; ni < 2; ++ni)
                wmma::store_matrix_sync(C + (size_t)(m0 + wm * 64 + mi * 16) * N + n0 + wn * 32 + ni * 16,
                                        acc[mi][ni], N, wmma::mem_row_major);
        return;
    }

    // stage acc tile to smem (row stride EPS words)
    float* ep = (float*)dsm;
#pragma unroll
    for (int mi = 0; mi < 4; ++mi)
#pragma unroll
        for (int ni = 0; ni < 2; ++ni)
            wmma::store_matrix_sync(ep + (wm * 64 + mi * 16) * EPS + wn * 32 + ni * 16,
                                    acc[mi][ni], EPS, wmma::mem_row_major);
    __syncthreads();

    if (epi_mode == 1) {
        // per-row L2 norm (tile N-width 128 == one head)
        if (tid < 128) {
            float ss = 0.f;
#pragma unroll 8
            for (int i = 0; i < 128; ++i) {
                float v = ep[tid * EPS + i];
                ss = fmaf(v, v, ss);
            }
            sc[tid] = 1.f / fmaxf(sqrtf(ss), 1e-12f);
        }
        __syncthreads();
        const int r = tid >> 1, c0 = (tid & 1) * 64;
        const float s = sc[r];
        const size_t row = m0 + r;
        float* Cp = C + row * N + n0 + c0;
        __nv_bfloat16* H = bt.eh[z] + row * bt.estride[z] + bt.ecol[z] + n0 + c0;
        __nv_bfloat16* L = bt.el[z] + row * bt.estride[z] + bt.ecol[z] + n0 + c0;
#pragma unroll
        for (int j = 0; j < 16; ++j) {
            float4 v = *(float4*)(ep + r * EPS + c0 + j * 4);
            split4_store(v, H, L, j * 4);              // raw split (for generator)
            v.x *= s; v.y *= s; v.z *= s; v.w *= s;    // normalized (for recurrence)
            *(float4*)(Cp + j * 4) = v;
        }
    } else if (epi_mode == 2) {
        const int r = tid >> 1, c0 = (tid & 1) * 64;
        const size_t row = m0 + r;
        __nv_bfloat16* H = bt.eh[z] + row * bt.estride[z] + n0 + c0;
        __nv_bfloat16* L = bt.el[z] + row * bt.estride[z] + n0 + c0;
#pragma unroll
        for (int j = 0; j < 16; ++j) {
            float4 v = *(float4*)(ep + r * EPS + c0 + j * 4);
            v.x = v.x * sigmoidf_(v.x);
            v.y = v.y * sigmoidf_(v.y);
            v.z = v.z * sigmoidf_(v.z);
            v.w = v.w * sigmoidf_(v.w);
            split4_store(v, H, L, j * 4);
        }
    } else {
        // EPI 3: dynamic conv. acc tile holds kern[rows m0..m0+127][n0..n0+127],
        // col = d_local*4 + w, d = n0/4 + d_local (32 d-channels, all 4 taps).
        const int dd = tid & 31;
        const int rb = (tid >> 5) * 16;
        const int d = (n0 >> 2) + dd;
        const float4 bb = *(const float4*)(bt.bias + n0 + dd * 4);
        const float* vcol = bt.vsrc + d;
        float vw0, vw1, vw2, vw3;
        {
            int row0 = m0 + rb;
            int tl = row0 & 2047;
            vw0 = (tl >= 3) ? vcol[(size_t)(row0 - 3) * 2048] : 0.f;
            vw1 = (tl >= 2) ? vcol[(size_t)(row0 - 2) * 2048] : 0.f;
            vw2 = (tl >= 1) ? vcol[(size_t)(row0 - 1) * 2048] : 0.f;
        }
#pragma unroll
        for (int i = 0; i < 16; ++i) {
            const int row = m0 + rb + i;
            const int tl = row & 2047;
            vw3 = vcol[(size_t)row * 2048];
            float4 kf = *(const float4*)(ep + (rb + i) * EPS + dd * 4);
            kf.x += bb.x; kf.y += bb.y; kf.z += bb.z; kf.w += bb.w;
            float a0 = (tl >= 3) ? vw0 : 0.f;
            float a1 = (tl >= 2) ? vw1 : 0.f;
            float a2 = (tl >= 1) ? vw2 : 0.f;
            float acc2 = kf.x * a0 + kf.y * a1 + kf.z * a2 + kf.w * vw3;
            C[(size_t)row * 2048 + d] = acc2 * sigmoidf_(acc2);
            vw0 = vw1; vw1 = vw2; vw2 = vw3;
        }
    }
}

// ---------------------------------------------------------------------------
// beta / decay
// ---------------------------------------------------------------------------
__global__ void __launch_bounds__(256) betag_kernel(
    const float* __restrict__ x, const float* __restrict__ Wb, const float* __restrict__ Wa,
    const float* __restrict__ dtb, const float* __restrict__ Alog,
    float* __restrict__ beta, float* __restrict__ decay)
{
    __shared__ float xs[16][128];
    __shared__ float wbs[128 * 17];
    __shared__ float was[128 * 17];
    const int tid = threadIdx.x;
    const int myrow = tid >> 4, mycol = tid & 15;
    const int r0 = blockIdx.x * 16;
    float pb = 0.f, pa = 0.f;
    for (int ch = 0; ch < 16; ++ch) {
        __syncthreads();
#pragma unroll
        for (int j = 0; j < 8; ++j) {
            int lin = tid + j * 256;
            int rr = lin >> 7, cc = lin & 127;
            xs[rr][cc] = x[(size_t)(r0 + rr) * 2048 + ch * 128 + cc];
            int wi = lin >> 4, wc = lin & 15;
            wbs[wi * 17 + wc] = Wb[(size_t)ch * 2048 + lin];
            was[wi * 17 + wc] = Wa[(size_t)ch * 2048 + lin];
        }
        __syncthreads();
#pragma unroll 8
        for (int i = 0; i < 128; ++i) {
            float xv = xs[myrow][i];
            pb = fmaf(xv, wbs[i * 17 + mycol], pb);
            pa = fmaf(xv, was[i * 17 + mycol], pa);
        }
    }
    int row = r0 + myrow;
    beta[row * 16 + mycol] = 1.f / (1.f + expf(-pb));
    float z = pa + dtb[mycol];
    float sp = (z > 20.f) ? z : log1pf(expf(z));
    decay[row * 16 + mycol] = expf(-expf(Alog[mycol]) * sp);
}

// ---------------------------------------------------------------------------
// Gated delta rule recurrence, time-tiled with cp.async (unchanged from R6)
// ---------------------------------------------------------------------------
#define TT 16
__global__ void __launch_bounds__(256, 1) recur_kernel(
    const float* __restrict__ qn, const float* __restrict__ kn,
    const float* __restrict__ v, const float* __restrict__ decay,
    const float* __restrict__ beta, float* __restrict__ o)
{
    __shared__ float qt[2][TT * 128];
    __shared__ float kt[2][TT * 128];
    __shared__ float vt[2][TT * 32];
    __shared__ float gt[2][TT];
    __shared__ float bt[2][TT];
    __shared__ float ob[TT * 32];

    const int bx = blockIdx.x;
    const int bh = bx >> 2;
    const int dvblk = bx & 3;
    const int b = bh >> 4;
    const int h = bh & 15;
    const int tid = threadIdx.x;
    const int dkg = tid & 7;
    const int dvi = tid >> 3;

    const size_t row0 = (size_t)b * 2048;
    const float* qrow = qn + row0 * 2048 + h * 128;
    const float* krow = kn + row0 * 2048 + h * 128;
    const float* vrow = v + row0 * 2048 + h * 128 + dvblk * 32;
    const float* grow = decay + row0 * 16 + h;
    const float* brow = beta + row0 * 16 + h;
    float* obase = o + row0 * 2048 + h * 128 + dvblk * 32;

    float S[16];
#pragma unroll
    for (int i = 0; i < 16; ++i) S[i] = 0.f;

    auto issue_tile = [&](int tt, int buf) {
        const int t0 = tt * TT;
#pragma unroll
        for (int j = 0; j < 2; ++j) {
            int c = tid + j * 256;
            int st = c >> 5, of = c & 31;
            cp16(smem_u32(&qt[buf][st * 128 + of * 4]),
                 qrow + (size_t)(t0 + st) * 2048 + of * 4);
            cp16(smem_u32(&kt[buf][st * 128 + of * 4]),
                 krow + (size_t)(t0 + st) * 2048 + of * 4);
        }
        if (tid < 128) {
            int st = tid >> 3, of = tid & 7;
            cp16(smem_u32(&vt[buf][st * 32 + of * 4]),
                 vrow + (size_t)(t0 + st) * 2048 + of * 4);
        } else if (tid < 144) {
            int i = tid - 128;
            cp4(smem_u32(&gt[buf][i]), grow + (size_t)(t0 + i) * 16);
        } else if (tid < 160) {
            int i = tid - 144;
            cp4(smem_u32(&bt[buf][i]), brow + (size_t)(t0 + i) * 16);
        }
    };

    issue_tile(0, 0);
    asm volatile("cp.async.commit_group;");

    const int NT = 2048 / TT;
    for (int tt = 0; tt < NT; ++tt) {
        asm volatile("cp.async.wait_group 0;");
        __syncthreads();
        const int buf = tt & 1;
        if (tt + 1 < NT) issue_tile(tt + 1, buf ^ 1);
        asm volatile("cp.async.commit_group;");

#pragma unroll 4
        for (int st = 0; st < TT; ++st) {
            float qv[16], kv[16];
#pragma unroll
            for (int j = 0; j < 4; ++j) {
                float4 a = *(const float4*)&qt[buf][st * 128 + (dkg + 8 * j) * 4];
                qv[j * 4 + 0] = a.x; qv[j * 4 + 1] = a.y; qv[j * 4 + 2] = a.z; qv[j * 4 + 3] = a.w;
                float4 c = *(const float4*)&kt[buf][st * 128 + (dkg + 8 * j) * 4];
                kv[j * 4 + 0] = c.x; kv[j * 4 + 1] = c.y; kv[j * 4 + 2] = c.z; kv[j * 4 + 3] = c.w;
            }
            float o0 = 0.f, o1 = 0.f, s0 = 0.f, s1 = 0.f;
#pragma unroll
            for (int i = 0; i < 16; i += 2) {
                o0 = fmaf(S[i],     qv[i],     o0);
                o1 = fmaf(S[i + 1], qv[i + 1], o1);
                s0 = fmaf(S[i],     kv[i],     s0);
                s1 = fmaf(S[i + 1], kv[i + 1], s1);
            }
            float ot = o0 + o1, sk = s0 + s1;
#pragma unroll
            for (int m = 4; m >= 1; m >>= 1) {
                ot += __shfl_xor_sync(0xffffffffu, ot, m);
                sk += __shfl_xor_sync(0xffffffffu, sk, m);
            }
            const float gv = gt[buf][st];
            const float bv = bt[buf][st];
            const float vv = vt[buf][st * 32 + dvi];
            const float cc = bv * (vv - sk);
#pragma unroll
            for (int i = 0; i < 16; ++i)
                S[i] = fmaf(cc, kv[i], S[i] * gv);
            if (dkg == 0) ob[st * 32 + dvi] = ot;
        }
        __syncthreads();
        if (tid < 128) {
            int st = tid >> 3, of = tid & 7;
            float4 val = *(const float4*)&ob[st * 32 + of * 4];
            *(float4*)(obase + (size_t)(tt * TT + st) * 2048 + of * 4) = val;
        }
    }
}

// ---------------------------------------------------------------------------
// Gated RMSNorm -> split bf16 directly (no fp32 og)
// ---------------------------------------------------------------------------
__global__ void __launch_bounds__(256) rmsgate_kernel(
    const float* __restrict__ o, const float* __restrict__ xg,
    const float* __restrict__ nw,
    __nv_bfloat16* __restrict__ H, __nv_bfloat16* __restrict__ L)
{
    int u = blockIdx.x * 8 + (threadIdx.x >> 5);
    int lane = threadIdx.x & 31;
    size_t base = (size_t)u * 128 + lane * 4;
    float4 a = *(const float4*)(o + base);
    float ss = a.x * a.x + a.y * a.y + a.z * a.z + a.w * a.w;
#pragma unroll
    for (int m = 16; m >= 1; m >>= 1) ss += __shfl_xor_sync(0xffffffffu, ss, m);
    float r = rsqrtf(ss * (1.f / 128.f) + 1e-6f);
    float4 g = *(const float4*)(xg + base);
    float4 w = *(const float4*)(nw + lane * 4);
    float4 out;
    out.x = a.x * r * w.x * (g.x * sigmoidf_(g.x));
    out.y = a.y * r * w.y * (g.y * sigmoidf_(g.y));
    out.z = a.z * r * w.z * (g.z * sigmoidf_(g.z));
    out.w = a.w * r * w.w * (g.w * sigmoidf_(g.w));
    split4_store(out, H, L, base);
}

// ---------------------------------------------------------------------------
extern "C" void kernel_launch(void* const* d_in, const int* in_sizes, int n_in,
                              void* d_out, int out_size)
{
    const float* x    = (const float*)d_in[0];
    const float* Wq   = (const float*)d_in[1];
    const float* Wk   = (const float*)d_in[2];
    const float* Wv   = (const float*)d_in[3];
    const float* Wb   = (const float*)d_in[4];
    const float* Wa   = (const float*)d_in[5];
    const float* dtb  = (const float*)d_in[6];
    const float* Alog = (const float*)d_in[7];
    const float* W1   = (const float*)d_in[8];
    const float* W2   = (const float*)d_in[9];
    const float* b2   = (const float*)d_in[10];
    const float* nw   = (const float*)d_in[11];
    const float* Wg   = (const float*)d_in[12];
    const float* Wo   = (const float*)d_in[13];
    float* out = (float*)d_out;

    float *q, *k, *v, *v2, *o, *xg, *beta, *decay;
    __nv_bfloat16 *wth, *wtl, *p0h, *p0l, *pqh, *pql;
    cudaGetSymbolAddress((void**)&q,     g_q);
    cudaGetSymbolAddress((void**)&k,     g_k);
    cudaGetSymbolAddress((void**)&v,     g_v);
    cudaGetSymbolAddress((void**)&v2,    g_v2);
    cudaGetSymbolAddress((void**)&o,     g_o);
    cudaGetSymbolAddress((void**)&xg,    g_xg);
    cudaGetSymbolAddress((void**)&beta,  g_beta);
    cudaGetSymbolAddress((void**)&decay, g_decay);
    cudaGetSymbolAddress((void**)&wth,   g_wth);
    cudaGetSymbolAddress((void**)&wtl,   g_wtl);
    cudaGetSymbolAddress((void**)&p0h,   g_p0h);
    cudaGetSymbolAddress((void**)&p0l,   g_p0l);
    cudaGetSymbolAddress((void**)&pqh,   g_pqh);
    cudaGetSymbolAddress((void**)&pql,   g_pql);

    const int SMEM = 81920;
    cudaFuncSetAttribute(gemm_cp, cudaFuncAttributeMaxDynamicSharedMemorySize, SMEM);

    // 0) weight prep
    {
        PrepBatch pb{};
        pb.W[0] = Wq;  pb.off[0] = OFF_Q;
        pb.W[1] = Wk;  pb.off[1] = OFF_K;
        pb.W[2] = Wv;  pb.off[2] = OFF_V;
        pb.W[3] = Wg;  pb.off[3] = OFF_G;
        pb.W[4] = Wo;  pb.off[4] = OFF_WO;
        prep_kernel<<<dim3(64, 64, 5), 256>>>(pb, wth, wtl, 2048, 2048);
        PrepBatch p1{};
        p1.W[0] = W1;  p1.off[0] = OFF_W1;
        prep_kernel<<<dim3(64, 128, 1), 256>>>(p1, wth, wtl, 2048, 4096);
        PrepBatch p2{};
        p2.W[0] = W2;  p2.off[0] = OFF_W2;
        prep_kernel<<<dim3(256, 64, 1), 256>>>(p2, wth, wtl, 8192, 2048);
    }
    // 0b) split x
    split_kernel<<<8192, 256>>>(x, p0h, p0l);
    // 1) fused projections: q,k (EPI1: norm + raw split), v, xg (EPI0)
    {
        GB bt{};
        for (int z = 0; z < 4; ++z) { bt.Ah[z] = p0h; bt.Al[z] = p0l; }
        bt.Bh[0] = wth + OFF_Q; bt.Bh[1] = wth + OFF_K; bt.Bh[2] = wth + OFF_V; bt.Bh[3] = wth + OFF_G;
        bt.Bl[0] = wtl + OFF_Q; bt.Bl[1] = wtl + OFF_K; bt.Bl[2] = wtl + OFF_V; bt.Bl[3] = wtl + OFF_G;
        bt.C[0] = q; bt.C[1] = k; bt.C[2] = v; bt.C[3] = xg;
        bt.epi[0] = 1; bt.epi[1] = 1; bt.epi[2] = 0; bt.epi[3] = 0;
        bt.eh[0] = pqh; bt.el[0] = pql; bt.estride[0] = 4096; bt.ecol[0] = 0;
        bt.eh[1] = pqh; bt.el[1] = pql; bt.estride[1] = 4096; bt.ecol[1] = 2048;
        gemm_cp<<<dim3(16, 32, 4), 256, SMEM>>>(bt, 4096, 2048, 2048);
    }
    betag_kernel<<<256, 256>>>(x, Wb, Wa, dtb, Alog, beta, decay);
    // 2) generator layer 1 (K=4096 over raw concat(q,k)); EPI2: silu + split
    {
        GB bt{};
        bt.Ah[0] = pqh; bt.Al[0] = pql;
        bt.Bh[0] = wth + OFF_W1; bt.Bl[0] = wtl + OFF_W1;
        bt.C[0] = nullptr;
        bt.epi[0] = 2;
        bt.eh[0] = p0h; bt.el[0] = p0l; bt.estride[0] = 2048; bt.ecol[0] = 0;
        gemm_cp<<<dim3(16, 32, 1), 256, SMEM>>>(bt, 4096, 2048, 4096);
    }
    // 3) generator layer 2 + fused bias + dynamic conv + SiLU -> v2 (EPI3)
    {
        GB bt{};
        bt.Ah[0] = p0h; bt.Al[0] = p0l;
        bt.Bh[0] = wth + OFF_W2; bt.Bl[0] = wtl + OFF_W2;
        bt.C[0] = v2;
        bt.epi[0] = 3;
        bt.vsrc = v; bt.bias = b2;
        gemm_cp<<<dim3(64, 32, 1), 256, SMEM>>>(bt, 4096, 8192, 2048);
    }
    // 4) recurrence (q,k already normalized by proj epilogue)
    recur_kernel<<<128, 256>>>(q, k, v2, decay, beta, o);
    // 5) gated RMSNorm -> og split (p0 free after gen2)
    rmsgate_kernel<<<8192, 256>>>(o, xg, nw, p0h, p0l);
    // 6) output projection
    {
        GB bt{};
        bt.Ah[0] = p0h; bt.Al[0] = p0l;
        bt.Bh[0] = wth + OFF_WO; bt.Bl[0] = wtl + OFF_WO;
        bt.C[0] = out;
        bt.epi[0] = 0;
        gemm_cp<<<dim3(16, 32, 1), 256, SMEM>>>(bt, 4096, 2048, 2048);
    }
}